// round 5
// baseline (speedup 1.0000x reference)
#include <cuda_runtime.h>
#include <cstdint>

// ---------------- problem constants ----------------
#define NW   960          // windows
#define NT   144          // tokens per window
#define DIMM 192          // embedding dim
#define NH   6            // heads
#define HD   32           // head dim
#define NQKV 576          // 3*DIMM
#define MROWS (NW*NT)     // 138240 total tokens
#define QSCALE 0.17677669529663689f   // 32^-0.5
#define BIAS_ELEMS (NH*NT*NT)         // 124416

// ---------------- scratch (static device globals; no allocation) ----------------
__device__ float g_q[NW*NH*NT*HD];     // [w][h][n][d], pre-scaled by QSCALE
__device__ float g_k[NW*NH*NT*HD];     // [w][h][n][d]
__device__ float g_v[NW*NH*NT*HD];     // [w][h][n][d]
__device__ float g_ctx[MROWS*DIMM];    // [w][n][h*32+d]  (attention output)
__device__ float g_bias[BIAS_ELEMS];   // [h][n][m]

// ---------------- kernel 0: expand relative-position bias ----------------
__global__ void bias_expand_kernel(const int* __restrict__ rel,
                                   const float* __restrict__ table) {
    int id = blockIdx.x * 256 + threadIdx.x;
    if (id >= BIAS_ELEMS) return;
    int h  = id / (NT * NT);
    int nm = id - h * (NT * NT);
    g_bias[id] = table[rel[nm] * NH + h];
}

// ---------------- generic SGEMM: C[M,N] = A[M,192] @ B[192,N] + bias ----------------
// BM=128, BN=64, BK=16, 256 threads, 8x4 microtile per thread (strided 16x16 map).
// EPI==0 : QKV projection epilogue (scatter into g_q/g_k/g_v, scale q)
// EPI==1 : output projection epilogue (write dense C)
template <int EPI>
__global__ __launch_bounds__(256)
void sgemm_kernel(const float* __restrict__ A, const float* __restrict__ B,
                  const float* __restrict__ bias, float* __restrict__ C,
                  int ldb) {
    __shared__ float As[16 * 130];   // [k][m], stride 130 (pad: conflict-free)
    __shared__ float Bs[16 * 64];    // [k][n]

    const int tid = threadIdx.x;
    const int tx  = tid & 15;        // col group
    const int ty  = tid >> 4;        // row group
    const int m0  = blockIdx.y * 128;
    const int n0  = blockIdx.x * 64;

    const float* Ap = (EPI == 0) ? A : g_ctx;

    float acc[8][4];
#pragma unroll
    for (int i = 0; i < 8; i++)
#pragma unroll
        for (int j = 0; j < 4; j++) acc[i][j] = 0.f;

    const int ar = tid >> 2;   // 0..63  (A row within pass)
    const int aq = tid & 3;    // 0..3   (A k-quad)
    const int bk = tid >> 4;   // 0..15  (B k row)
    const int bc = tid & 15;   // 0..15  (B col quad)

    for (int k0 = 0; k0 < 192; k0 += 16) {
        // load A tile (128x16), transposed into As[k][m]
#pragma unroll
        for (int p = 0; p < 2; p++) {
            const int row = ar + 64 * p;
            float4 a = *(const float4*)&Ap[(size_t)(m0 + row) * 192 + k0 + aq * 4];
            As[(aq * 4 + 0) * 130 + row] = a.x;
            As[(aq * 4 + 1) * 130 + row] = a.y;
            As[(aq * 4 + 2) * 130 + row] = a.z;
            As[(aq * 4 + 3) * 130 + row] = a.w;
        }
        // load B tile (16x64)
        float4 b = *(const float4*)&B[(size_t)(k0 + bk) * ldb + n0 + bc * 4];
        *(float4*)&Bs[bk * 64 + bc * 4] = b;
        __syncthreads();

#pragma unroll
        for (int kk = 0; kk < 16; kk++) {
            float af[8], bf[4];
#pragma unroll
            for (int i = 0; i < 8; i++) af[i] = As[kk * 130 + ty + 16 * i];
#pragma unroll
            for (int j = 0; j < 4; j++) bf[j] = Bs[kk * 64 + tx + 16 * j];
#pragma unroll
            for (int i = 0; i < 8; i++)
#pragma unroll
                for (int j = 0; j < 4; j++)
                    acc[i][j] += af[i] * bf[j];
        }
        __syncthreads();
    }

    // epilogue
#pragma unroll
    for (int i = 0; i < 8; i++) {
        const int m = m0 + ty + 16 * i;
#pragma unroll
        for (int j = 0; j < 4; j++) {
            const int n = n0 + tx + 16 * j;
            float v = acc[i][j] + bias[n];
            if (EPI == 0) {
                const int w    = m / NT;
                const int tok  = m - w * NT;
                const int comp = n / DIMM;            // 0=q 1=k 2=v
                const int rem  = n - comp * DIMM;
                const int h    = rem >> 5;
                const int d    = rem & 31;
                const int idx  = (((w * NH + h) * NT + tok) << 5) + d;
                if (comp == 0)      g_q[idx] = v * QSCALE;
                else if (comp == 1) g_k[idx] = v;
                else                g_v[idx] = v;
            } else {
                C[(size_t)m * DIMM + n] = v;
            }
        }
    }
}

// ---------------- fused attention: one block per (window, head) ----------------
// smem: q[144*33] k[144*33] v[144*32] p[144*145]  = 139,968 bytes
__global__ __launch_bounds__(256, 1)
void attn_kernel(const int* __restrict__ mask) {
    extern __shared__ float sm[];
    float* q_s = sm;                       // stride 33 (conflict-free)
    float* k_s = q_s + NT * 33;
    float* v_s = k_s + NT * 33;            // stride 32 (float2-aligned)
    float* p_s = v_s + NT * 32;            // stride 145 (conflict-free)

    const int blk = blockIdx.x;
    const int w   = blk / NH;
    const int h   = blk - w * NH;
    const int tid = threadIdx.x;

    const int base = ((w * NH + h) * NT) << 5;   // offset into g_q/g_k/g_v
    for (int i = tid; i < NT * HD; i += 256) {
        const int n = i >> 5, d = i & 31;
        q_s[n * 33 + d] = g_q[base + i];
        k_s[n * 33 + d] = g_k[base + i];
        v_s[i]          = g_v[base + i];
    }
    __syncthreads();

    // ---- scores: S[n][m] = q[n]·k[m]  (q pre-scaled) ----
    {
        const int tx = tid & 15;   // m group
        const int ty = tid >> 4;   // n group
        float acc[9][9];
#pragma unroll
        for (int i = 0; i < 9; i++)
#pragma unroll
            for (int j = 0; j < 9; j++) acc[i][j] = 0.f;

#pragma unroll 4
        for (int d = 0; d < 32; d++) {
            float qa[9], kb[9];
#pragma unroll
            for (int i = 0; i < 9; i++) qa[i] = q_s[(ty + 16 * i) * 33 + d];
#pragma unroll
            for (int j = 0; j < 9; j++) kb[j] = k_s[(tx + 16 * j) * 33 + d];
#pragma unroll
            for (int i = 0; i < 9; i++)
#pragma unroll
                for (int j = 0; j < 9; j++)
                    acc[i][j] += qa[i] * kb[j];
        }
#pragma unroll
        for (int i = 0; i < 9; i++)
#pragma unroll
            for (int j = 0; j < 9; j++)
                p_s[(ty + 16 * i) * 145 + tx + 16 * j] = acc[i][j];
    }
    __syncthreads();

    // ---- bias + mask + softmax (one warp per row) ----
    {
        const int lane = tid & 31;
        const int wid  = tid >> 5;
        const float* brow_base = g_bias + h * NT * NT;
        const int*   mrow_base = mask + (size_t)w * NT * NT;
#pragma unroll 1
        for (int k = 0; k < 18; k++) {
            const int n = wid + 8 * k;
            float*       pr = p_s + n * 145;
            const float* br = brow_base + n * NT;
            const int*   mr = mrow_base + n * NT;

            float mx = -3.0e38f;
            for (int m = lane; m < NT; m += 32) {
                float s = pr[m] + br[m];
                if (mr[m] == 0) s = -1.0e9f;
                pr[m] = s;
                mx = fmaxf(mx, s);
            }
#pragma unroll
            for (int off = 16; off; off >>= 1)
                mx = fmaxf(mx, __shfl_xor_sync(0xffffffffu, mx, off));

            float sum = 0.f;
            for (int m = lane; m < NT; m += 32) {
                float e = __expf(pr[m] - mx);
                pr[m] = e;
                sum += e;
            }
#pragma unroll
            for (int off = 16; off; off >>= 1)
                sum += __shfl_xor_sync(0xffffffffu, sum, off);

            const float inv = 1.f / sum;
            for (int m = lane; m < NT; m += 32) pr[m] *= inv;
        }
    }
    __syncthreads();

    // ---- PV: out[n][d] = sum_m P[n][m] * v[m][d] ----
    {
        const int dx = tid & 15;        // d pair: d0 = 2*dx
        const int ny = tid >> 4;        // n group
        float o[9][2];
#pragma unroll
        for (int k = 0; k < 9; k++) { o[k][0] = 0.f; o[k][1] = 0.f; }

#pragma unroll 4
        for (int m = 0; m < NT; m++) {
            const float2 vv = *(const float2*)&v_s[m * 32 + dx * 2];
#pragma unroll
            for (int k = 0; k < 9; k++) {
                const float pp = p_s[(ny + 16 * k) * 145 + m];
                o[k][0] += pp * vv.x;
                o[k][1] += pp * vv.y;
            }
        }
#pragma unroll
        for (int k = 0; k < 9; k++) {
            const int n = ny + 16 * k;
            const int oidx = (((w * NT + n) * NH + h) << 5) + dx * 2;
            *(float2*)&g_ctx[oidx] = make_float2(o[k][0], o[k][1]);
        }
    }
}

// ---------------- launch ----------------
extern "C" void kernel_launch(void* const* d_in, const int* in_sizes, int n_in,
                              void* d_out, int out_size) {
    const float* x      = (const float*)d_in[0];
    const int*   mask   = (const int*)  d_in[1];
    const int*   rel    = (const int*)  d_in[2];
    const float* w_qkv  = (const float*)d_in[3];
    const float* b_qkv  = (const float*)d_in[4];
    const float* w_out  = (const float*)d_in[5];
    const float* b_out  = (const float*)d_in[6];
    const float* btab   = (const float*)d_in[7];
    float*       out    = (float*)d_out;

    // Launch on the stream that is actually being captured (per-thread) if a
    // capture is active; otherwise the legacy default stream.
    cudaStream_t stream = cudaStreamLegacy;
    cudaStreamCaptureStatus st = cudaStreamCaptureStatusNone;
    if (cudaStreamIsCapturing(cudaStreamPerThread, &st) == cudaSuccess &&
        st == cudaStreamCaptureStatusActive) {
        stream = cudaStreamPerThread;
    }

    const int ATTN_SMEM = (NT * 33 * 2 + NT * 32 + NT * 145) * (int)sizeof(float); // 139968
    cudaFuncSetAttribute(attn_kernel,
                         cudaFuncAttributeMaxDynamicSharedMemorySize, ATTN_SMEM);

    // 0) bias expansion
    bias_expand_kernel<<<(BIAS_ELEMS + 255) / 256, 256, 0, stream>>>(rel, btab);

    // 1) QKV projection (+ scatter + q scaling)
    {
        dim3 grid(NQKV / 64, MROWS / 128);   // (9, 1080)
        sgemm_kernel<0><<<grid, 256, 0, stream>>>(x, w_qkv, b_qkv, nullptr, NQKV);
    }

    // 2) fused window attention
    attn_kernel<<<NW * NH, 256, ATTN_SMEM, stream>>>(mask);

    // 3) output projection
    {
        dim3 grid(DIMM / 64, MROWS / 128);   // (3, 1080)
        sgemm_kernel<1><<<grid, 256, 0, stream>>>(nullptr, w_out, b_out, out, DIMM);
    }
}

// round 7
// speedup vs baseline: 1.7416x; 1.7416x over previous
#include <cuda_runtime.h>
#include <cstdint>

#define NW   960
#define NT   144
#define DIMM 192
#define NH   6
#define HD   32
#define NQKV 576
#define MROWS (NW*NT)
#define QSCALE 0.17677669529663689f
#define BIAS_ELEMS (NH*NT*NT)

__device__ float g_q[NW*NH*NT*HD];
__device__ float g_k[NW*NH*NT*HD];
__device__ float g_v[NW*NH*NT*HD];
__device__ float g_ctx[MROWS*DIMM];
__device__ float g_bias[BIAS_ELEMS];

// ---------------- bias expansion ----------------
__global__ void bias_expand_kernel(const int* __restrict__ rel,
                                   const float* __restrict__ table) {
    int id = blockIdx.x * 256 + threadIdx.x;
    if (id >= BIAS_ELEMS) return;
    int h  = id / (NT * NT);
    int nm = id - h * (NT * NT);
    g_bias[id] = table[rel[nm] * NH + h];
}

// ---------------- SGEMM: C[M,N] = A[M,192] @ B[192,N] + bias ----------------
// BM=128 BN=64 BK=16, 256 thr. Microtile 8x4, rows contiguous (ty*8+i),
// cols one float4 (tx*4). Inner loop: 2 LDS.128 (A, broadcast) + 1 LDS.128 (B)
// per 32 FFMA. As stride 132 -> 528B rows, 16B-aligned for LDS.128.
template <int EPI>
__global__ __launch_bounds__(256)
void sgemm_kernel(const float* __restrict__ A, const float* __restrict__ B,
                  const float* __restrict__ bias, float* __restrict__ C,
                  int ldb) {
    __shared__ float As[16 * 132];
    __shared__ float Bs[16 * 64];

    const int tid = threadIdx.x;
    const int tx  = tid & 15;        // col quad
    const int ty  = tid >> 4;        // row group (8 contiguous rows)
    const int m0  = blockIdx.y * 128;
    const int n0  = blockIdx.x * 64;

    const float* Ap = (EPI == 0) ? A : g_ctx;

    float acc[8][4];
#pragma unroll
    for (int i = 0; i < 8; i++)
#pragma unroll
        for (int j = 0; j < 4; j++) acc[i][j] = 0.f;

    const int ar = tid >> 2;   // 0..63
    const int aq = tid & 3;    // 0..3
    const int bk = tid >> 4;
    const int bc = tid & 15;

    for (int k0 = 0; k0 < 192; k0 += 16) {
#pragma unroll
        for (int p = 0; p < 2; p++) {
            const int row = ar + 64 * p;
            float4 a = *(const float4*)&Ap[(size_t)(m0 + row) * 192 + k0 + aq * 4];
            As[(aq * 4 + 0) * 132 + row] = a.x;
            As[(aq * 4 + 1) * 132 + row] = a.y;
            As[(aq * 4 + 2) * 132 + row] = a.z;
            As[(aq * 4 + 3) * 132 + row] = a.w;
        }
        *(float4*)&Bs[bk * 64 + bc * 4] =
            *(const float4*)&B[(size_t)(k0 + bk) * ldb + n0 + bc * 4];
        __syncthreads();

#pragma unroll
        for (int kk = 0; kk < 16; kk++) {
            float4 a0 = *(const float4*)&As[kk * 132 + ty * 8];
            float4 a1 = *(const float4*)&As[kk * 132 + ty * 8 + 4];
            float4 bf = *(const float4*)&Bs[kk * 64 + tx * 4];
            const float af[8] = {a0.x, a0.y, a0.z, a0.w, a1.x, a1.y, a1.z, a1.w};
            const float bb[4] = {bf.x, bf.y, bf.z, bf.w};
#pragma unroll
            for (int i = 0; i < 8; i++)
#pragma unroll
                for (int j = 0; j < 4; j++)
                    acc[i][j] += af[i] * bb[j];
        }
        __syncthreads();
    }

    // epilogue: one float4 per output row
    const int n    = n0 + tx * 4;
    const float4 bi = *(const float4*)&bias[n];
#pragma unroll
    for (int i = 0; i < 8; i++) {
        const int m = m0 + ty * 8 + i;
        float4 v = make_float4(acc[i][0] + bi.x, acc[i][1] + bi.y,
                               acc[i][2] + bi.z, acc[i][3] + bi.w);
        if (EPI == 0) {
            const int comp = n0 / DIMM;          // whole block same component
            const int rem  = n - comp * DIMM;
            const int h    = rem >> 5;
            const int d    = rem & 31;           // quad-aligned, no 32-crossing
            const int w    = m / NT;
            const int tok  = m - w * NT;
            const int idx  = (((w * NH + h) * NT + tok) << 5) + d;
            if (comp == 0) {
                v.x *= QSCALE; v.y *= QSCALE; v.z *= QSCALE; v.w *= QSCALE;
                *(float4*)&g_q[idx] = v;
            } else if (comp == 1) *(float4*)&g_k[idx] = v;
            else                  *(float4*)&g_v[idx] = v;
        } else {
            *(float4*)&C[(size_t)m * DIMM + n] = v;
        }
    }
}

// ---------------- attention: 3 blocks per (w,h), 48 q-rows each ----------------
// smem: q[48][34] k[144][34] v[144][32] p[48][148] = 72,960 B -> 3 CTAs/SM
__global__ __launch_bounds__(256)
void attn_kernel(const int* __restrict__ mask) {
    extern __shared__ float sm[];
    float* q_s = sm;                  // [48][34]
    float* k_s = q_s + 48 * 34;       // [144][34]
    float* v_s = k_s + NT * 34;       // [144][32]
    float* p_s = v_s + NT * 32;       // [48][148]

    const int b   = blockIdx.x;
    const int seg = b % 3;
    const int wh  = b / 3;
    const int h   = wh % NH;
    const int w   = wh / NH;
    const int tid = threadIdx.x;
    const int n0  = seg * 48;

    const int base = ((w * NH + h) * NT) << 5;
    for (int i = tid; i < NT * HD; i += 256) {
        const int n = i >> 5, d = i & 31;
        k_s[n * 34 + d] = g_k[base + i];
        v_s[i]          = g_v[base + i];
    }
    for (int i = tid; i < 48 * HD; i += 256) {
        const int n = i >> 5, d = i & 31;
        q_s[n * 34 + d] = g_q[base + n0 * HD + i];
    }
    __syncthreads();

    // ---- S = q k^T : 3x9 microtile, float2 d-pairs ----
    {
        const int tx = tid & 15;   // m group
        const int ty = tid >> 4;   // n group
        float acc[3][9];
#pragma unroll
        for (int i = 0; i < 3; i++)
#pragma unroll
            for (int j = 0; j < 9; j++) acc[i][j] = 0.f;

#pragma unroll
        for (int d2 = 0; d2 < 16; d2++) {
            float2 qa[3], kb[9];
#pragma unroll
            for (int i = 0; i < 3; i++)
                qa[i] = *(const float2*)&q_s[(ty + 16 * i) * 34 + 2 * d2];
#pragma unroll
            for (int j = 0; j < 9; j++)
                kb[j] = *(const float2*)&k_s[(tx + 16 * j) * 34 + 2 * d2];
#pragma unroll
            for (int i = 0; i < 3; i++)
#pragma unroll
                for (int j = 0; j < 9; j++)
                    acc[i][j] += qa[i].x * kb[j].x + qa[i].y * kb[j].y;
        }
#pragma unroll
        for (int i = 0; i < 3; i++)
#pragma unroll
            for (int j = 0; j < 9; j++)
                p_s[(ty + 16 * i) * 148 + tx + 16 * j] = acc[i][j];
    }
    __syncthreads();

    // ---- bias + mask + softmax: one warp per row, 6 rows/warp ----
    {
        const int lane = tid & 31;
        const int wr   = tid >> 5;
        const float* bb = g_bias + h * NT * NT;
        const int*   mm = mask + (size_t)w * NT * NT;
#pragma unroll 1
        for (int t = 0; t < 6; t++) {
            const int n = wr + 8 * t;
            float*       pr = p_s + n * 148;
            const float* br = bb + (n0 + n) * NT;
            const int*   mr = mm + (n0 + n) * NT;

            float mx = -3.0e38f;
            for (int m = lane; m < NT; m += 32) {
                float s = pr[m] + br[m];
                if (mr[m] == 0) s = -1.0e9f;
                pr[m] = s;
                mx = fmaxf(mx, s);
            }
#pragma unroll
            for (int off = 16; off; off >>= 1)
                mx = fmaxf(mx, __shfl_xor_sync(0xffffffffu, mx, off));

            float sum = 0.f;
            for (int m = lane; m < NT; m += 32) {
                float e = __expf(pr[m] - mx);
                pr[m] = e;
                sum += e;
            }
#pragma unroll
            for (int off = 16; off; off >>= 1)
                sum += __shfl_xor_sync(0xffffffffu, sum, off);

            const float inv = 1.f / sum;
            for (int m = lane; m < NT; m += 32) pr[m] *= inv;
        }
    }
    __syncthreads();

    // ---- PV: 3 rows x 1 d-pair per thread, 4-m inner steps ----
    {
        const int tx = tid & 15;   // d pair
        const int ty = tid >> 4;   // row group
        float ox[3] = {0.f, 0.f, 0.f}, oy[3] = {0.f, 0.f, 0.f};

#pragma unroll 2
        for (int m = 0; m < NT; m += 4) {
            float2 v0 = *(const float2*)&v_s[(m + 0) * 32 + 2 * tx];
            float2 v1 = *(const float2*)&v_s[(m + 1) * 32 + 2 * tx];
            float2 v2 = *(const float2*)&v_s[(m + 2) * 32 + 2 * tx];
            float2 v3 = *(const float2*)&v_s[(m + 3) * 32 + 2 * tx];
#pragma unroll
            for (int k = 0; k < 3; k++) {
                float4 pp = *(const float4*)&p_s[(ty + 16 * k) * 148 + m];
                ox[k] += pp.x * v0.x + pp.y * v1.x + pp.z * v2.x + pp.w * v3.x;
                oy[k] += pp.x * v0.y + pp.y * v1.y + pp.z * v2.y + pp.w * v3.y;
            }
        }
#pragma unroll
        for (int k = 0; k < 3; k++) {
            const int n = n0 + ty + 16 * k;
            const int oidx = (w * NT + n) * DIMM + h * HD + 2 * tx;
            *(float2*)&g_ctx[oidx] = make_float2(ox[k], oy[k]);
        }
    }
}

// ---------------- launch ----------------
extern "C" void kernel_launch(void* const* d_in, const int* in_sizes, int n_in,
                              void* d_out, int out_size) {
    const float* x      = (const float*)d_in[0];
    const int*   mask   = (const int*)  d_in[1];
    const int*   rel    = (const int*)  d_in[2];
    const float* w_qkv  = (const float*)d_in[3];
    const float* b_qkv  = (const float*)d_in[4];
    const float* w_out  = (const float*)d_in[5];
    const float* b_out  = (const float*)d_in[6];
    const float* btab   = (const float*)d_in[7];
    float*       out    = (float*)d_out;

    cudaStream_t stream = cudaStreamLegacy;
    cudaStreamCaptureStatus st = cudaStreamCaptureStatusNone;
    if (cudaStreamIsCapturing(cudaStreamPerThread, &st) == cudaSuccess &&
        st == cudaStreamCaptureStatusActive) {
        stream = cudaStreamPerThread;
    }

    const int ATTN_SMEM = (48 * 34 + NT * 34 + NT * 32 + 48 * 148) * 4; // 72960
    cudaFuncSetAttribute(attn_kernel,
                         cudaFuncAttributeMaxDynamicSharedMemorySize, ATTN_SMEM);

    bias_expand_kernel<<<(BIAS_ELEMS + 255) / 256, 256, 0, stream>>>(rel, btab);

    {
        dim3 grid(NQKV / 64, MROWS / 128);
        sgemm_kernel<0><<<grid, 256, 0, stream>>>(x, w_qkv, b_qkv, nullptr, NQKV);
    }

    attn_kernel<<<NW * NH * 3, 256, ATTN_SMEM, stream>>>(mask);

    {
        dim3 grid(DIMM / 64, MROWS / 128);
        sgemm_kernel<1><<<grid, 256, 0, stream>>>(nullptr, w_out, b_out, out, DIMM);
    }
}

// round 9
// speedup vs baseline: 1.8377x; 1.0552x over previous
#include <cuda_runtime.h>
#include <cstdint>

#define NW   960
#define NT   144
#define DIMM 192
#define NH   6
#define HD   32
#define NQKV 576
#define MROWS (NW*NT)
#define QSCALE 0.17677669529663689f
#define BIAS_ELEMS (NH*NT*NT)

__device__ float g_q[NW*NH*NT*HD];
__device__ float g_k[NW*NH*NT*HD];
__device__ float g_v[NW*NH*NT*HD];
__device__ float g_ctx[MROWS*DIMM];
__device__ float g_bias[BIAS_ELEMS];

// ---------------- bias expansion ----------------
__global__ void bias_expand_kernel(const int* __restrict__ rel,
                                   const float* __restrict__ table) {
    int id = blockIdx.x * 256 + threadIdx.x;
    if (id >= BIAS_ELEMS) return;
    int h  = id / (NT * NT);
    int nm = id - h * (NT * NT);
    g_bias[id] = table[rel[nm] * NH + h];
}

// ---------------- SGEMM (unchanged from R7-passing): C = A@B + bias ----------------
template <int EPI>
__global__ __launch_bounds__(256)
void sgemm_kernel(const float* __restrict__ A, const float* __restrict__ B,
                  const float* __restrict__ bias, float* __restrict__ C,
                  int ldb) {
    __shared__ float As[16 * 132];
    __shared__ float Bs[16 * 64];

    const int tid = threadIdx.x;
    const int tx  = tid & 15;
    const int ty  = tid >> 4;
    const int m0  = blockIdx.y * 128;
    const int n0  = blockIdx.x * 64;

    const float* Ap = (EPI == 0) ? A : g_ctx;

    float acc[8][4];
#pragma unroll
    for (int i = 0; i < 8; i++)
#pragma unroll
        for (int j = 0; j < 4; j++) acc[i][j] = 0.f;

    const int ar = tid >> 2;
    const int aq = tid & 3;
    const int bk = tid >> 4;
    const int bc = tid & 15;

    for (int k0 = 0; k0 < 192; k0 += 16) {
#pragma unroll
        for (int p = 0; p < 2; p++) {
            const int row = ar + 64 * p;
            float4 a = *(const float4*)&Ap[(size_t)(m0 + row) * 192 + k0 + aq * 4];
            As[(aq * 4 + 0) * 132 + row] = a.x;
            As[(aq * 4 + 1) * 132 + row] = a.y;
            As[(aq * 4 + 2) * 132 + row] = a.z;
            As[(aq * 4 + 3) * 132 + row] = a.w;
        }
        *(float4*)&Bs[bk * 64 + bc * 4] =
            *(const float4*)&B[(size_t)(k0 + bk) * ldb + n0 + bc * 4];
        __syncthreads();

#pragma unroll
        for (int kk = 0; kk < 16; kk++) {
            float4 a0 = *(const float4*)&As[kk * 132 + ty * 8];
            float4 a1 = *(const float4*)&As[kk * 132 + ty * 8 + 4];
            float4 bf = *(const float4*)&Bs[kk * 64 + tx * 4];
            const float af[8] = {a0.x, a0.y, a0.z, a0.w, a1.x, a1.y, a1.z, a1.w};
            const float bb[4] = {bf.x, bf.y, bf.z, bf.w};
#pragma unroll
            for (int i = 0; i < 8; i++)
#pragma unroll
                for (int j = 0; j < 4; j++)
                    acc[i][j] += af[i] * bb[j];
        }
        __syncthreads();
    }

    const int n    = n0 + tx * 4;
    const float4 bi = *(const float4*)&bias[n];
#pragma unroll
    for (int i = 0; i < 8; i++) {
        const int m = m0 + ty * 8 + i;
        float4 v = make_float4(acc[i][0] + bi.x, acc[i][1] + bi.y,
                               acc[i][2] + bi.z, acc[i][3] + bi.w);
        if (EPI == 0) {
            const int comp = n0 / DIMM;
            const int rem  = n - comp * DIMM;
            const int h    = rem >> 5;
            const int d    = rem & 31;
            const int w    = m / NT;
            const int tok  = m - w * NT;
            const int idx  = (((w * NH + h) * NT + tok) << 5) + d;
            if (comp == 0) {
                v.x *= QSCALE; v.y *= QSCALE; v.z *= QSCALE; v.w *= QSCALE;
                *(float4*)&g_q[idx] = v;
            } else if (comp == 1) *(float4*)&g_k[idx] = v;
            else                  *(float4*)&g_v[idx] = v;
        } else {
            *(float4*)&C[(size_t)m * DIMM + n] = v;
        }
    }
}

// ---------------- attention: 3 blocks per (w,h); register-fused softmax ----------------
// smem: q[48][34] k[144][34] v[144][32] p[48][148] = 72,960 B -> 3 CTAs/SM
__global__ __launch_bounds__(256)
void attn_kernel(const int* __restrict__ mask) {
    extern __shared__ float sm[];
    float* q_s = sm;
    float* k_s = q_s + 48 * 34;
    float* v_s = k_s + NT * 34;
    float* p_s = v_s + NT * 32;

    const int b = blockIdx.x, seg = b % 3, wh = b / 3;
    const int h = wh % NH, w = wh / NH;
    const int tid = threadIdx.x, n0 = seg * 48;

    const int base = ((w * NH + h) * NT) << 5;
    for (int i = tid; i < NT * HD; i += 256) {
        const int n = i >> 5, d = i & 31;
        k_s[n * 34 + d] = g_k[base + i];
        v_s[i]          = g_v[base + i];
    }
    for (int i = tid; i < 48 * HD; i += 256) {
        const int n = i >> 5, d = i & 31;
        q_s[n * 34 + d] = g_q[base + n0 * HD + i];
    }
    __syncthreads();

    // ---- QK^T (3x9 microtile) + bias/mask + register softmax, one p_s write ----
    {
        const int tx = tid & 15;   // m group
        const int ty = tid >> 4;   // n group
        float acc[3][9];
#pragma unroll
        for (int i = 0; i < 3; i++)
#pragma unroll
            for (int j = 0; j < 9; j++) acc[i][j] = 0.f;

#pragma unroll
        for (int d2 = 0; d2 < 16; d2++) {
            float2 qa[3], kb[9];
#pragma unroll
            for (int i = 0; i < 3; i++)
                qa[i] = *(const float2*)&q_s[(ty + 16 * i) * 34 + 2 * d2];
#pragma unroll
            for (int j = 0; j < 9; j++)
                kb[j] = *(const float2*)&k_s[(tx + 16 * j) * 34 + 2 * d2];
#pragma unroll
            for (int i = 0; i < 3; i++)
#pragma unroll
                for (int j = 0; j < 9; j++)
                    acc[i][j] += qa[i].x * kb[j].x + qa[i].y * kb[j].y;
        }

        // bias + mask loads (54 independent LDGs, high MLP)
        const float* bb = g_bias + h * NT * NT;
        const int*   mm = mask + (size_t)w * NT * NT;
        float bv[3][9]; int mv[3][9];
#pragma unroll
        for (int i = 0; i < 3; i++) {
            const int n = n0 + ty + 16 * i;
#pragma unroll
            for (int j = 0; j < 9; j++) {
                const int m = tx + 16 * j;
                bv[i][j] = bb[n * NT + m];
                mv[i][j] = mm[n * NT + m];
            }
        }

#pragma unroll
        for (int i = 0; i < 3; i++) {
            float s[9];
#pragma unroll
            for (int j = 0; j < 9; j++) {
                float t = acc[i][j] + bv[i][j];
                s[j] = (mv[i][j] != 0) ? t : -1.0e9f;
            }
            float mx = s[0];
#pragma unroll
            for (int j = 1; j < 9; j++) mx = fmaxf(mx, s[j]);
#pragma unroll
            for (int o = 8; o; o >>= 1)
                mx = fmaxf(mx, __shfl_xor_sync(0xffffffffu, mx, o));

            float sum = 0.f;
#pragma unroll
            for (int j = 0; j < 9; j++) {
                s[j] = __expf(s[j] - mx);
                sum += s[j];
            }
#pragma unroll
            for (int o = 8; o; o >>= 1)
                sum += __shfl_xor_sync(0xffffffffu, sum, o);
            const float inv = 1.f / sum;

            float* pr = p_s + (ty + 16 * i) * 148;
#pragma unroll
            for (int j = 0; j < 9; j++)
                pr[tx + 16 * j] = s[j] * inv;
        }
    }
    __syncthreads();

    // ---- PV: 3 rows x 1 d-pair per thread ----
    {
        const int tx = tid & 15, ty = tid >> 4;
        float ox[3] = {0.f, 0.f, 0.f}, oy[3] = {0.f, 0.f, 0.f};
#pragma unroll 2
        for (int m = 0; m < NT; m += 4) {
            float2 v0 = *(const float2*)&v_s[(m + 0) * 32 + 2 * tx];
            float2 v1 = *(const float2*)&v_s[(m + 1) * 32 + 2 * tx];
            float2 v2 = *(const float2*)&v_s[(m + 2) * 32 + 2 * tx];
            float2 v3 = *(const float2*)&v_s[(m + 3) * 32 + 2 * tx];
#pragma unroll
            for (int k = 0; k < 3; k++) {
                float4 pp = *(const float4*)&p_s[(ty + 16 * k) * 148 + m];
                ox[k] += pp.x * v0.x + pp.y * v1.x + pp.z * v2.x + pp.w * v3.x;
                oy[k] += pp.x * v0.y + pp.y * v1.y + pp.z * v2.y + pp.w * v3.y;
            }
        }
#pragma unroll
        for (int k = 0; k < 3; k++) {
            const int n = n0 + ty + 16 * k;
            const int oidx = (w * NT + n) * DIMM + h * HD + 2 * tx;
            *(float2*)&g_ctx[oidx] = make_float2(ox[k], oy[k]);
        }
    }
}

// ---------------- launch ----------------
extern "C" void kernel_launch(void* const* d_in, const int* in_sizes, int n_in,
                              void* d_out, int out_size) {
    const float* x     = (const float*)d_in[0];
    const int*   mask  = (const int*)  d_in[1];
    const int*   rel   = (const int*)  d_in[2];
    const float* w_qkv = (const float*)d_in[3];
    const float* b_qkv = (const float*)d_in[4];
    const float* w_out = (const float*)d_in[5];
    const float* b_out = (const float*)d_in[6];
    const float* btab  = (const float*)d_in[7];
    float*       out   = (float*)d_out;

    cudaStream_t stream = cudaStreamLegacy;
    cudaStreamCaptureStatus st = cudaStreamCaptureStatusNone;
    if (cudaStreamIsCapturing(cudaStreamPerThread, &st) == cudaSuccess &&
        st == cudaStreamCaptureStatusActive) {
        stream = cudaStreamPerThread;
    }

    const int ATTN_SMEM = (48 * 34 + NT * 34 + NT * 32 + 48 * 148) * 4; // 72960
    cudaFuncSetAttribute(attn_kernel,
                         cudaFuncAttributeMaxDynamicSharedMemorySize, ATTN_SMEM);

    bias_expand_kernel<<<(BIAS_ELEMS + 255) / 256, 256, 0, stream>>>(rel, btab);

    {
        dim3 grid(NQKV / 64, MROWS / 128);
        sgemm_kernel<0><<<grid, 256, 0, stream>>>(x, w_qkv, b_qkv, nullptr, NQKV);
    }

    attn_kernel<<<NW * NH * 3, 256, ATTN_SMEM, stream>>>(mask);

    {
        dim3 grid(DIMM / 64, MROWS / 128);
        sgemm_kernel<1><<<grid, 256, 0, stream>>>(nullptr, w_out, b_out, out, DIMM);
    }
}

// round 10
// speedup vs baseline: 2.2256x; 1.2111x over previous
#include <cuda_runtime.h>
#include <cstdint>

#define NW   960
#define NT   144
#define DIMM 192
#define NH   6
#define HD   32
#define NQKV 576
#define MROWS (NW*NT)
#define QSCALE 0.17677669529663689f
#define BIAS_ELEMS (NH*NT*NT)

__device__ float g_q[NW*NH*NT*HD];
__device__ float g_k[NW*NH*NT*HD];
__device__ float g_v[NW*NH*NT*HD];
__device__ float g_ctx[MROWS*DIMM];
__device__ float g_bias[BIAS_ELEMS];

// ---------------- bias expansion ----------------
__global__ void bias_expand_kernel(const int* __restrict__ rel,
                                   const float* __restrict__ table) {
    int id = blockIdx.x * 256 + threadIdx.x;
    if (id >= BIAS_ELEMS) return;
    int h  = id / (NT * NT);
    int nm = id - h * (NT * NT);
    g_bias[id] = table[rel[nm] * NH + h];
}

// ---------------- SGEMM, double-buffered: C = A@B + bias ----------------
// BM=128 BN=64 BK=16, 256 thr, 8x4 microtile. 2-stage smem, 1 barrier/step,
// gmem prefetch overlapped with compute.
template <int EPI>
__global__ __launch_bounds__(256)
void sgemm_kernel(const float* __restrict__ A, const float* __restrict__ B,
                  const float* __restrict__ bias, float* __restrict__ C,
                  int ldb) {
    __shared__ float As[2][16 * 132];
    __shared__ float Bs[2][16 * 64];

    const int tid = threadIdx.x;
    const int tx  = tid & 15;
    const int ty  = tid >> 4;
    const int m0  = blockIdx.y * 128;
    const int n0  = blockIdx.x * 64;

    const float* Ap = (EPI == 0) ? A : g_ctx;

    float acc[8][4];
#pragma unroll
    for (int i = 0; i < 8; i++)
#pragma unroll
        for (int j = 0; j < 4; j++) acc[i][j] = 0.f;

    const int ar = tid >> 2;   // 0..63
    const int aq = tid & 3;    // 0..3
    const int bk = tid >> 4;
    const int bc = tid & 15;

    // prologue: stage 0
    {
        float4 a0 = *(const float4*)&Ap[(size_t)(m0 + ar) * 192 + aq * 4];
        float4 a1 = *(const float4*)&Ap[(size_t)(m0 + ar + 64) * 192 + aq * 4];
        float4 b  = *(const float4*)&B[(size_t)bk * ldb + n0 + bc * 4];
        As[0][(aq * 4 + 0) * 132 + ar] = a0.x;
        As[0][(aq * 4 + 1) * 132 + ar] = a0.y;
        As[0][(aq * 4 + 2) * 132 + ar] = a0.z;
        As[0][(aq * 4 + 3) * 132 + ar] = a0.w;
        As[0][(aq * 4 + 0) * 132 + ar + 64] = a1.x;
        As[0][(aq * 4 + 1) * 132 + ar + 64] = a1.y;
        As[0][(aq * 4 + 2) * 132 + ar + 64] = a1.z;
        As[0][(aq * 4 + 3) * 132 + ar + 64] = a1.w;
        *(float4*)&Bs[0][bk * 64 + bc * 4] = b;
    }
    __syncthreads();

    float4 a0n, a1n, bn;
#pragma unroll 1
    for (int it = 0; it < 12; it++) {
        const int s = it & 1;
        if (it < 11) {
            const int k0 = 16 * (it + 1);
            a0n = *(const float4*)&Ap[(size_t)(m0 + ar) * 192 + k0 + aq * 4];
            a1n = *(const float4*)&Ap[(size_t)(m0 + ar + 64) * 192 + k0 + aq * 4];
            bn  = *(const float4*)&B[(size_t)(k0 + bk) * ldb + n0 + bc * 4];
        }
#pragma unroll
        for (int kk = 0; kk < 16; kk++) {
            float4 f0 = *(const float4*)&As[s][kk * 132 + ty * 8];
            float4 f1 = *(const float4*)&As[s][kk * 132 + ty * 8 + 4];
            float4 bf = *(const float4*)&Bs[s][kk * 64 + tx * 4];
            const float af[8] = {f0.x, f0.y, f0.z, f0.w, f1.x, f1.y, f1.z, f1.w};
            const float bb[4] = {bf.x, bf.y, bf.z, bf.w};
#pragma unroll
            for (int i = 0; i < 8; i++)
#pragma unroll
                for (int j = 0; j < 4; j++)
                    acc[i][j] += af[i] * bb[j];
        }
        if (it < 11) {
            const int d = s ^ 1;
            As[d][(aq * 4 + 0) * 132 + ar] = a0n.x;
            As[d][(aq * 4 + 1) * 132 + ar] = a0n.y;
            As[d][(aq * 4 + 2) * 132 + ar] = a0n.z;
            As[d][(aq * 4 + 3) * 132 + ar] = a0n.w;
            As[d][(aq * 4 + 0) * 132 + ar + 64] = a1n.x;
            As[d][(aq * 4 + 1) * 132 + ar + 64] = a1n.y;
            As[d][(aq * 4 + 2) * 132 + ar + 64] = a1n.z;
            As[d][(aq * 4 + 3) * 132 + ar + 64] = a1n.w;
            *(float4*)&Bs[d][bk * 64 + bc * 4] = bn;
        }
        __syncthreads();
    }

    const int n    = n0 + tx * 4;
    const float4 bi = *(const float4*)&bias[n];
#pragma unroll
    for (int i = 0; i < 8; i++) {
        const int m = m0 + ty * 8 + i;
        float4 v = make_float4(acc[i][0] + bi.x, acc[i][1] + bi.y,
                               acc[i][2] + bi.z, acc[i][3] + bi.w);
        if (EPI == 0) {
            const int comp = n0 / DIMM;
            const int rem  = n - comp * DIMM;
            const int h    = rem >> 5;
            const int d    = rem & 31;
            const int w    = m / NT;
            const int tok  = m - w * NT;
            const int idx  = (((w * NH + h) * NT + tok) << 5) + d;
            if (comp == 0) {
                v.x *= QSCALE; v.y *= QSCALE; v.z *= QSCALE; v.w *= QSCALE;
                *(float4*)&g_q[idx] = v;
            } else if (comp == 1) *(float4*)&g_k[idx] = v;
            else                  *(float4*)&g_v[idx] = v;
        } else {
            *(float4*)&C[(size_t)m * DIMM + n] = v;
        }
    }
}

// ---------------- attention: 3 blocks per (w,h); row-wise fused softmax ----------------
// smem: q[48][34] k[144][34] v[144][32] p[48][148] = 72,960 B -> 3 CTAs/SM pinned
__global__ __launch_bounds__(256, 3)
void attn_kernel(const int* __restrict__ mask) {
    extern __shared__ float sm[];
    float* q_s = sm;
    float* k_s = q_s + 48 * 34;
    float* v_s = k_s + NT * 34;
    float* p_s = v_s + NT * 32;

    const int b = blockIdx.x, seg = b % 3, wh = b / 3;
    const int h = wh % NH, w = wh / NH;
    const int tid = threadIdx.x, n0 = seg * 48;

    const int base = ((w * NH + h) * NT) << 5;
    for (int i = tid; i < NT * HD; i += 256) {
        const int n = i >> 5, d = i & 31;
        k_s[n * 34 + d] = g_k[base + i];
        v_s[i]          = g_v[base + i];
    }
    for (int i = tid; i < 48 * HD; i += 256) {
        const int n = i >> 5, d = i & 31;
        q_s[n * 34 + d] = g_q[base + n0 * HD + i];
    }
    __syncthreads();

    // ---- QK^T (3x9 microtile), then per-row bias/mask/softmax ----
    {
        const int tx = tid & 15;   // m group
        const int ty = tid >> 4;   // n group
        float acc[3][9];
#pragma unroll
        for (int i = 0; i < 3; i++)
#pragma unroll
            for (int j = 0; j < 9; j++) acc[i][j] = 0.f;

#pragma unroll
        for (int d2 = 0; d2 < 16; d2++) {
            float2 qa[3], kb[9];
#pragma unroll
            for (int i = 0; i < 3; i++)
                qa[i] = *(const float2*)&q_s[(ty + 16 * i) * 34 + 2 * d2];
#pragma unroll
            for (int j = 0; j < 9; j++)
                kb[j] = *(const float2*)&k_s[(tx + 16 * j) * 34 + 2 * d2];
#pragma unroll
            for (int i = 0; i < 3; i++)
#pragma unroll
                for (int j = 0; j < 9; j++)
                    acc[i][j] += qa[i].x * kb[j].x + qa[i].y * kb[j].y;
        }

        const float* bb = g_bias + h * NT * NT;
        const int*   mm = mask + (size_t)w * NT * NT;
#pragma unroll
        for (int i = 0; i < 3; i++) {
            const int n = n0 + ty + 16 * i;
            float bv[9]; int mv[9];
#pragma unroll
            for (int j = 0; j < 9; j++) {
                bv[j] = bb[n * NT + tx + 16 * j];
                mv[j] = mm[n * NT + tx + 16 * j];
            }
            float s[9];
#pragma unroll
            for (int j = 0; j < 9; j++) {
                float t = acc[i][j] + bv[j];
                s[j] = (mv[j] != 0) ? t : -1.0e9f;
            }
            float mx = s[0];
#pragma unroll
            for (int j = 1; j < 9; j++) mx = fmaxf(mx, s[j]);
#pragma unroll
            for (int o = 8; o; o >>= 1)
                mx = fmaxf(mx, __shfl_xor_sync(0xffffffffu, mx, o));

            float sum = 0.f;
#pragma unroll
            for (int j = 0; j < 9; j++) {
                s[j] = __expf(s[j] - mx);
                sum += s[j];
            }
#pragma unroll
            for (int o = 8; o; o >>= 1)
                sum += __shfl_xor_sync(0xffffffffu, sum, o);
            const float inv = 1.f / sum;

            float* pr = p_s + (ty + 16 * i) * 148;
#pragma unroll
            for (int j = 0; j < 9; j++)
                pr[tx + 16 * j] = s[j] * inv;
        }
    }
    __syncthreads();

    // ---- PV: 3 rows x 1 d-pair per thread ----
    {
        const int tx = tid & 15, ty = tid >> 4;
        float ox[3] = {0.f, 0.f, 0.f}, oy[3] = {0.f, 0.f, 0.f};
#pragma unroll 2
        for (int m = 0; m < NT; m += 4) {
            float2 v0 = *(const float2*)&v_s[(m + 0) * 32 + 2 * tx];
            float2 v1 = *(const float2*)&v_s[(m + 1) * 32 + 2 * tx];
            float2 v2 = *(const float2*)&v_s[(m + 2) * 32 + 2 * tx];
            float2 v3 = *(const float2*)&v_s[(m + 3) * 32 + 2 * tx];
#pragma unroll
            for (int k = 0; k < 3; k++) {
                float4 pp = *(const float4*)&p_s[(ty + 16 * k) * 148 + m];
                ox[k] += pp.x * v0.x + pp.y * v1.x + pp.z * v2.x + pp.w * v3.x;
                oy[k] += pp.x * v0.y + pp.y * v1.y + pp.z * v2.y + pp.w * v3.y;
            }
        }
#pragma unroll
        for (int k = 0; k < 3; k++) {
            const int n = n0 + ty + 16 * k;
            const int oidx = (w * NT + n) * DIMM + h * HD + 2 * tx;
            *(float2*)&g_ctx[oidx] = make_float2(ox[k], oy[k]);
        }
    }
}

// ---------------- launch ----------------
extern "C" void kernel_launch(void* const* d_in, const int* in_sizes, int n_in,
                              void* d_out, int out_size) {
    const float* x     = (const float*)d_in[0];
    const int*   mask  = (const int*)  d_in[1];
    const int*   rel   = (const int*)  d_in[2];
    const float* w_qkv = (const float*)d_in[3];
    const float* b_qkv = (const float*)d_in[4];
    const float* w_out = (const float*)d_in[5];
    const float* b_out = (const float*)d_in[6];
    const float* btab  = (const float*)d_in[7];
    float*       out   = (float*)d_out;

    cudaStream_t stream = cudaStreamLegacy;
    cudaStreamCaptureStatus st = cudaStreamCaptureStatusNone;
    if (cudaStreamIsCapturing(cudaStreamPerThread, &st) == cudaSuccess &&
        st == cudaStreamCaptureStatusActive) {
        stream = cudaStreamPerThread;
    }

    const int ATTN_SMEM = (48 * 34 + NT * 34 + NT * 32 + 48 * 148) * 4; // 72960
    cudaFuncSetAttribute(attn_kernel,
                         cudaFuncAttributeMaxDynamicSharedMemorySize, ATTN_SMEM);

    bias_expand_kernel<<<(BIAS_ELEMS + 255) / 256, 256, 0, stream>>>(rel, btab);

    {
        dim3 grid(NQKV / 64, MROWS / 128);
        sgemm_kernel<0><<<grid, 256, 0, stream>>>(x, w_qkv, b_qkv, nullptr, NQKV);
    }

    attn_kernel<<<NW * NH * 3, 256, ATTN_SMEM, stream>>>(mask);

    {
        dim3 grid(DIMM / 64, MROWS / 128);
        sgemm_kernel<1><<<grid, 256, 0, stream>>>(nullptr, w_out, b_out, out, DIMM);
    }
}

// round 11
// speedup vs baseline: 2.8021x; 1.2590x over previous
#include <cuda_runtime.h>
#include <cuda_bf16.h>
#include <cstdint>

#define NW   960
#define NT   144
#define DIMM 192
#define NH   6
#define HD   32
#define NQKV 576
#define MROWS (NW*NT)
#define QSCALE 0.17677669529663689f
#define BIAS_ELEMS (NH*NT*NT)
#define MT16  (MROWS/16)          // 8640 m-tiles
#define KSTEPS 12                 // 192/16
#define A_PK  (MT16*KSTEPS*128)   // 13,271,040 uint32 per term

__device__ float g_q[NW*NH*NT*HD];
__device__ float g_k[NW*NH*NT*HD];
__device__ float g_v[NW*NH*NT*HD];
__device__ float g_ctx[MROWS*DIMM];
__device__ float g_bias[BIAS_ELEMS];
__device__ uint32_t g_xpk_hi[A_PK], g_xpk_lo[A_PK];
__device__ uint32_t g_cpk_hi[A_PK], g_cpk_lo[A_PK];
__device__ uint32_t g_wq_hi[9*12*512],  g_wq_lo[9*12*512];
__device__ uint32_t g_wo_hi[3*12*512],  g_wo_lo[3*12*512];

__device__ __forceinline__ uint32_t bfpack(float a, float b) {
    __nv_bfloat162 t = __floats2bfloat162_rn(a, b);
    return *reinterpret_cast<uint32_t*>(&t);
}
__device__ __forceinline__ void split2(float a, float b, uint32_t& hi, uint32_t& lo) {
    hi = bfpack(a, b);
    __nv_bfloat162 h = *reinterpret_cast<__nv_bfloat162*>(&hi);
    lo = bfpack(a - __bfloat162float(h.x), b - __bfloat162float(h.y));
}
__device__ __forceinline__ void mma_bf16(float* d, const uint32_t* a, const uint32_t* b) {
    asm volatile("mma.sync.aligned.m16n8k16.row.col.f32.bf16.bf16.f32 "
        "{%0,%1,%2,%3}, {%4,%5,%6,%7}, {%8,%9}, {%0,%1,%2,%3};"
        : "+f"(d[0]), "+f"(d[1]), "+f"(d[2]), "+f"(d[3])
        : "r"(a[0]), "r"(a[1]), "r"(a[2]), "r"(a[3]), "r"(b[0]), "r"(b[1]));
}

// A-fragment pack index for element pair (row m, cols k,k+1), k even.
__device__ __forceinline__ int apk_idx(int m, int k) {
    int mtile = m >> 4, mr = m & 15, kstep = k >> 4, kk = k & 15;
    int lane = (mr & 7) * 4 + ((kk & 7) >> 1);
    int reg  = ((mr >> 3) & 1) + ((kk >> 3) << 1);
    return ((mtile * KSTEPS + kstep) * 32 + lane) * 4 + reg;
}
// B-fragment pack index (col n, rows k,k+1 of K×N weight), k even.
__device__ __forceinline__ int bpk_idx(int n, int k) {
    int block = n >> 6, nl = n & 63, ntile = nl >> 3, g = nl & 7;
    int kstep = k >> 4, kk = k & 15;
    int lane = g * 4 + ((kk & 7) >> 1);
    int reg  = (kk >> 3) & 1;
    return ((block * KSTEPS + kstep) * 8 + ntile) * 64 + lane * 2 + reg;
}

// ---------------- prep: bias expand + weight packs ----------------
__global__ void prep_kernel(const int* __restrict__ rel, const float* __restrict__ table,
                            const float* __restrict__ w_qkv, const float* __restrict__ w_out) {
    int id = blockIdx.x * 256 + threadIdx.x;
    if (id < BIAS_ELEMS) {
        int h = id / (NT * NT), nm = id - h * (NT * NT);
        g_bias[id] = table[rel[nm] * NH + h];
    }
    if (id < NQKV * 96) {            // w_qkv pairs
        int n = id / 96, k = (id % 96) * 2;
        split2(w_qkv[k * NQKV + n], w_qkv[(k + 1) * NQKV + n],
               g_wq_hi[bpk_idx(n, k)], g_wq_lo[bpk_idx(n, k)]);
    }
    if (id < DIMM * 96) {            // w_out pairs
        int n = id / 96, k = (id % 96) * 2;
        split2(w_out[k * DIMM + n], w_out[(k + 1) * DIMM + n],
               g_wo_hi[bpk_idx(n, k)], g_wo_lo[bpk_idx(n, k)]);
    }
}

// ---------------- pack activations into fragment order ----------------
template <int SRC>   // 0: x (argument), 1: g_ctx
__global__ void pack_a_kernel(const float* __restrict__ x) {
    int id = blockIdx.x * 256 + threadIdx.x;    // pair id, grid covers A_PK exactly
    int m = id / 96, k = (id % 96) * 2;
    const float* src = (SRC == 0) ? x : g_ctx;
    float2 v = *(const float2*)&src[(size_t)m * DIMM + k];
    int idx = apk_idx(m, k);
    if (SRC == 0) split2(v.x, v.y, g_xpk_hi[idx], g_xpk_lo[idx]);
    else          split2(v.x, v.y, g_cpk_hi[idx], g_cpk_lo[idx]);
}

// ---------------- bf16-split tensor GEMM: 128x64 tile, 8 warps ----------------
// smem: A 2 stages x 1024 uint4, B 2 stages x 512 uint4 = 49152 B
template <int EPI>
__global__ __launch_bounds__(256)
void gemm_mma(const float* __restrict__ bias, float* __restrict__ C) {
    extern __shared__ uint4 smem4[];
    uint4* Asm = smem4;            // [2][1024]
    uint4* Bsm = smem4 + 2048;     // [2][512]

    const int tid = threadIdx.x, lane = tid & 31, wid = tid >> 5;
    const int wm = wid >> 1, wn = wid & 1;
    const int m0t = blockIdx.y * 8;              // base m-tile
    const int block = blockIdx.x;

    const uint4* Ahi = (const uint4*)((EPI == 0) ? g_xpk_hi : g_cpk_hi);
    const uint4* Alo = (const uint4*)((EPI == 0) ? g_xpk_lo : g_cpk_lo);
    const uint4* Bhi = (const uint4*)((EPI == 0) ? g_wq_hi  : g_wo_hi);
    const uint4* Blo = (const uint4*)((EPI == 0) ? g_wq_lo  : g_wo_lo);

    float acc[2][4][4];
#pragma unroll
    for (int mt = 0; mt < 2; mt++)
#pragma unroll
        for (int nt = 0; nt < 4; nt++)
#pragma unroll
            for (int r = 0; r < 4; r++) acc[mt][nt][r] = 0.f;

    auto a_gidx = [&](int u, int c) {   // u in [0,1024)
        int mt = (u & 511) >> 6, j = (u >> 5) & 1, q = u & 31;
        return ((m0t + mt) * KSTEPS + 2 * c + j) * 32 + q;
    };
    auto b_gidx = [&](int u, int c) {   // u in [0,512)
        int j = (u >> 7) & 1, nt = (u >> 4) & 7, q = u & 15;
        return ((block * KSTEPS + 2 * c + j) * 8 + nt) * 16 + q;
    };

    // prologue: stage 0
#pragma unroll
    for (int i = 0; i < 4; i++) {
        int u = tid + 256 * i;
        Asm[u] = (u < 512 ? Ahi : Alo)[a_gidx(u, 0)];
    }
#pragma unroll
    for (int i = 0; i < 2; i++) {
        int u = tid + 256 * i;
        Bsm[u] = (u < 256 ? Bhi : Blo)[b_gidx(u, 0)];
    }
    __syncthreads();

    uint4 pa[4], pb[2];
#pragma unroll 1
    for (int c = 0; c < 6; c++) {
        const int s = c & 1;
        if (c < 5) {
#pragma unroll
            for (int i = 0; i < 4; i++) {
                int u = tid + 256 * i;
                pa[i] = (u < 512 ? Ahi : Alo)[a_gidx(u, c + 1)];
            }
#pragma unroll
            for (int i = 0; i < 2; i++) {
                int u = tid + 256 * i;
                pb[i] = (u < 256 ? Bhi : Blo)[b_gidx(u, c + 1)];
            }
        }
        const uint4* As = Asm + s * 1024;
        const uint2* Bs2 = (const uint2*)(Bsm + s * 512);
#pragma unroll
        for (int j = 0; j < 2; j++) {
            uint4 ah[2], al[2];
#pragma unroll
            for (int mt = 0; mt < 2; mt++) {
                ah[mt] = As[(wm * 2 + mt) * 64 + j * 32 + lane];
                al[mt] = As[512 + (wm * 2 + mt) * 64 + j * 32 + lane];
            }
            uint2 bh[4], bl[4];
#pragma unroll
            for (int nt = 0; nt < 4; nt++) {
                bh[nt] = Bs2[(j * 8 + wn * 4 + nt) * 32 + lane];
                bl[nt] = Bs2[512 + (j * 8 + wn * 4 + nt) * 32 + lane];
            }
#pragma unroll
            for (int mt = 0; mt < 2; mt++)
#pragma unroll
                for (int nt = 0; nt < 4; nt++) {
                    mma_bf16(acc[mt][nt], (const uint32_t*)&ah[mt], (const uint32_t*)&bh[nt]);
                    mma_bf16(acc[mt][nt], (const uint32_t*)&ah[mt], (const uint32_t*)&bl[nt]);
                    mma_bf16(acc[mt][nt], (const uint32_t*)&al[mt], (const uint32_t*)&bh[nt]);
                }
        }
        if (c < 5) {
            uint4* Ad = Asm + (s ^ 1) * 1024;
            uint4* Bd = Bsm + (s ^ 1) * 512;
#pragma unroll
            for (int i = 0; i < 4; i++) Ad[tid + 256 * i] = pa[i];
#pragma unroll
            for (int i = 0; i < 2; i++) Bd[tid + 256 * i] = pb[i];
        }
        __syncthreads();
    }

    // epilogue
    const int g = lane >> 2, t = lane & 3;
#pragma unroll
    for (int mt = 0; mt < 2; mt++) {
        const int r0 = m0t * 16 + wm * 32 + mt * 16 + g;
#pragma unroll
        for (int nt = 0; nt < 4; nt++) {
            const int cn = wn * 32 + nt * 8 + 2 * t;          // col within 64-block
            const float2 bi = *(const float2*)&bias[block * 64 + cn];
            float2 v0 = make_float2(acc[mt][nt][0] + bi.x, acc[mt][nt][1] + bi.y);
            float2 v1 = make_float2(acc[mt][nt][2] + bi.x, acc[mt][nt][3] + bi.y);
            if (EPI == 0) {
                const int comp = block / 3;
                const int n = (block % 3) * 64 + cn;
                const int h = n >> 5, d = n & 31;
                float* dst = (comp == 0) ? g_q : (comp == 1 ? g_k : g_v);
                if (comp == 0) { v0.x *= QSCALE; v0.y *= QSCALE; v1.x *= QSCALE; v1.y *= QSCALE; }
                int w0 = r0 / NT, tok0 = r0 - w0 * NT;
                int r1 = r0 + 8, w1 = r1 / NT, tok1 = r1 - w1 * NT;
                *(float2*)&dst[(((w0 * NH + h) * NT + tok0) << 5) + d] = v0;
                *(float2*)&dst[(((w1 * NH + h) * NT + tok1) << 5) + d] = v1;
            } else {
                *(float2*)&C[(size_t)r0 * DIMM + block * 64 + cn] = v0;
                *(float2*)&C[(size_t)(r0 + 8) * DIMM + block * 64 + cn] = v1;
            }
        }
    }
}

// ---------------- attention (unchanged, R10-passing) ----------------
__global__ __launch_bounds__(256, 3)
void attn_kernel(const int* __restrict__ mask) {
    extern __shared__ float sm[];
    float* q_s = sm;
    float* k_s = q_s + 48 * 34;
    float* v_s = k_s + NT * 34;
    float* p_s = v_s + NT * 32;

    const int b = blockIdx.x, seg = b % 3, wh = b / 3;
    const int h = wh % NH, w = wh / NH;
    const int tid = threadIdx.x, n0 = seg * 48;

    const int base = ((w * NH + h) * NT) << 5;
    for (int i = tid; i < NT * HD; i += 256) {
        const int n = i >> 5, d = i & 31;
        k_s[n * 34 + d] = g_k[base + i];
        v_s[i]          = g_v[base + i];
    }
    for (int i = tid; i < 48 * HD; i += 256) {
        const int n = i >> 5, d = i & 31;
        q_s[n * 34 + d] = g_q[base + n0 * HD + i];
    }
    __syncthreads();

    {
        const int tx = tid & 15, ty = tid >> 4;
        float acc[3][9];
#pragma unroll
        for (int i = 0; i < 3; i++)
#pragma unroll
            for (int j = 0; j < 9; j++) acc[i][j] = 0.f;
#pragma unroll
        for (int d2 = 0; d2 < 16; d2++) {
            float2 qa[3], kb[9];
#pragma unroll
            for (int i = 0; i < 3; i++)
                qa[i] = *(const float2*)&q_s[(ty + 16 * i) * 34 + 2 * d2];
#pragma unroll
            for (int j = 0; j < 9; j++)
                kb[j] = *(const float2*)&k_s[(tx + 16 * j) * 34 + 2 * d2];
#pragma unroll
            for (int i = 0; i < 3; i++)
#pragma unroll
                for (int j = 0; j < 9; j++)
                    acc[i][j] += qa[i].x * kb[j].x + qa[i].y * kb[j].y;
        }
        const float* bb = g_bias + h * NT * NT;
        const int*   mm = mask + (size_t)w * NT * NT;
#pragma unroll
        for (int i = 0; i < 3; i++) {
            const int n = n0 + ty + 16 * i;
            float bv[9]; int mv[9];
#pragma unroll
            for (int j = 0; j < 9; j++) {
                bv[j] = bb[n * NT + tx + 16 * j];
                mv[j] = mm[n * NT + tx + 16 * j];
            }
            float s[9];
#pragma unroll
            for (int j = 0; j < 9; j++) {
                float tt = acc[i][j] + bv[j];
                s[j] = (mv[j] != 0) ? tt : -1.0e9f;
            }
            float mx = s[0];
#pragma unroll
            for (int j = 1; j < 9; j++) mx = fmaxf(mx, s[j]);
#pragma unroll
            for (int o = 8; o; o >>= 1)
                mx = fmaxf(mx, __shfl_xor_sync(0xffffffffu, mx, o));
            float sum = 0.f;
#pragma unroll
            for (int j = 0; j < 9; j++) { s[j] = __expf(s[j] - mx); sum += s[j]; }
#pragma unroll
            for (int o = 8; o; o >>= 1)
                sum += __shfl_xor_sync(0xffffffffu, sum, o);
            const float inv = 1.f / sum;
            float* pr = p_s + (ty + 16 * i) * 148;
#pragma unroll
            for (int j = 0; j < 9; j++)
                pr[tx + 16 * j] = s[j] * inv;
        }
    }
    __syncthreads();

    {
        const int tx = tid & 15, ty = tid >> 4;
        float ox[3] = {0.f, 0.f, 0.f}, oy[3] = {0.f, 0.f, 0.f};
#pragma unroll 2
        for (int m = 0; m < NT; m += 4) {
            float2 v0 = *(const float2*)&v_s[(m + 0) * 32 + 2 * tx];
            float2 v1 = *(const float2*)&v_s[(m + 1) * 32 + 2 * tx];
            float2 v2 = *(const float2*)&v_s[(m + 2) * 32 + 2 * tx];
            float2 v3 = *(const float2*)&v_s[(m + 3) * 32 + 2 * tx];
#pragma unroll
            for (int k = 0; k < 3; k++) {
                float4 pp = *(const float4*)&p_s[(ty + 16 * k) * 148 + m];
                ox[k] += pp.x * v0.x + pp.y * v1.x + pp.z * v2.x + pp.w * v3.x;
                oy[k] += pp.x * v0.y + pp.y * v1.y + pp.z * v2.y + pp.w * v3.y;
            }
        }
#pragma unroll
        for (int k = 0; k < 3; k++) {
            const int n = n0 + ty + 16 * k;
            const int oidx = (w * NT + n) * DIMM + h * HD + 2 * tx;
            *(float2*)&g_ctx[oidx] = make_float2(ox[k], oy[k]);
        }
    }
}

// ---------------- launch ----------------
extern "C" void kernel_launch(void* const* d_in, const int* in_sizes, int n_in,
                              void* d_out, int out_size) {
    const float* x     = (const float*)d_in[0];
    const int*   mask  = (const int*)  d_in[1];
    const int*   rel   = (const int*)  d_in[2];
    const float* w_qkv = (const float*)d_in[3];
    const float* b_qkv = (const float*)d_in[4];
    const float* w_out = (const float*)d_in[5];
    const float* b_out = (const float*)d_in[6];
    const float* btab  = (const float*)d_in[7];
    float*       out   = (float*)d_out;

    cudaStream_t stream = cudaStreamLegacy;
    cudaStreamCaptureStatus st = cudaStreamCaptureStatusNone;
    if (cudaStreamIsCapturing(cudaStreamPerThread, &st) == cudaSuccess &&
        st == cudaStreamCaptureStatusActive) {
        stream = cudaStreamPerThread;
    }

    const int ATTN_SMEM = (48 * 34 + NT * 34 + NT * 32 + 48 * 148) * 4; // 72960
    const int GEMM_SMEM = 49152;
    cudaFuncSetAttribute(attn_kernel,
                         cudaFuncAttributeMaxDynamicSharedMemorySize, ATTN_SMEM);
    cudaFuncSetAttribute(gemm_mma<0>,
                         cudaFuncAttributeMaxDynamicSharedMemorySize, GEMM_SMEM);
    cudaFuncSetAttribute(gemm_mma<1>,
                         cudaFuncAttributeMaxDynamicSharedMemorySize, GEMM_SMEM);

    prep_kernel<<<(BIAS_ELEMS + 255) / 256, 256, 0, stream>>>(rel, btab, w_qkv, w_out);
    pack_a_kernel<0><<<A_PK / 256, 256, 0, stream>>>(x);

    {
        dim3 grid(9, MROWS / 128);
        gemm_mma<0><<<grid, 256, GEMM_SMEM, stream>>>(b_qkv, nullptr);
    }

    attn_kernel<<<NW * NH * 3, 256, ATTN_SMEM, stream>>>(mask);

    pack_a_kernel<1><<<A_PK / 256, 256, 0, stream>>>(nullptr);
    {
        dim3 grid(3, MROWS / 128);
        gemm_mma<1><<<grid, 256, GEMM_SMEM, stream>>>(b_out, out);
    }
}

// round 12
// speedup vs baseline: 3.9976x; 1.4267x over previous
#include <cuda_runtime.h>
#include <cuda_bf16.h>
#include <cstdint>

#define NW   960
#define NT   144
#define DIMM 192
#define NH   6
#define HD   32
#define NQKV 576
#define MROWS (NW*NT)
#define QSCALE 0.17677669529663689f
#define BIAS_ELEMS (NH*NT*NT)
#define MT16  (MROWS/16)
#define KSTEPS 12
#define A_PK  (MT16*KSTEPS*128)

__device__ float g_q[NW*NH*NT*HD];
__device__ float g_k[NW*NH*NT*HD];
__device__ float g_v[NW*NH*NT*HD];
__device__ float g_ctx[MROWS*DIMM];
__device__ float g_bias[BIAS_ELEMS];
__device__ uint32_t g_xpk_hi[A_PK], g_xpk_lo[A_PK];
__device__ uint32_t g_cpk_hi[A_PK], g_cpk_lo[A_PK];
__device__ uint32_t g_wq_hi[9*12*512],  g_wq_lo[9*12*512];
__device__ uint32_t g_wo_hi[3*12*512],  g_wo_lo[3*12*512];

__device__ __forceinline__ uint32_t bfpack(float a, float b) {
    __nv_bfloat162 t = __floats2bfloat162_rn(a, b);
    return *reinterpret_cast<uint32_t*>(&t);
}
__device__ __forceinline__ void split2(float a, float b, uint32_t& hi, uint32_t& lo) {
    hi = bfpack(a, b);
    __nv_bfloat162 h = *reinterpret_cast<__nv_bfloat162*>(&hi);
    lo = bfpack(a - __bfloat162float(h.x), b - __bfloat162float(h.y));
}
__device__ __forceinline__ void mma_bf16(float* d, const uint32_t* a, const uint32_t* b) {
    asm volatile("mma.sync.aligned.m16n8k16.row.col.f32.bf16.bf16.f32 "
        "{%0,%1,%2,%3}, {%4,%5,%6,%7}, {%8,%9}, {%0,%1,%2,%3};"
        : "+f"(d[0]), "+f"(d[1]), "+f"(d[2]), "+f"(d[3])
        : "r"(a[0]), "r"(a[1]), "r"(a[2]), "r"(a[3]), "r"(b[0]), "r"(b[1]));
}

__device__ __forceinline__ int apk_idx(int m, int k) {
    int mtile = m >> 4, mr = m & 15, kstep = k >> 4, kk = k & 15;
    int lane = (mr & 7) * 4 + ((kk & 7) >> 1);
    int reg  = ((mr >> 3) & 1) + ((kk >> 3) << 1);
    return ((mtile * KSTEPS + kstep) * 32 + lane) * 4 + reg;
}
__device__ __forceinline__ int bpk_idx(int n, int k) {
    int block = n >> 6, nl = n & 63, ntile = nl >> 3, g = nl & 7;
    int kstep = k >> 4, kk = k & 15;
    int lane = g * 4 + ((kk & 7) >> 1);
    int reg  = (kk >> 3) & 1;
    return ((block * KSTEPS + kstep) * 8 + ntile) * 64 + lane * 2 + reg;
}

// ---------------- prep: bias expand + weight packs ----------------
__global__ void prep_kernel(const int* __restrict__ rel, const float* __restrict__ table,
                            const float* __restrict__ w_qkv, const float* __restrict__ w_out) {
    int id = blockIdx.x * 256 + threadIdx.x;
    if (id < BIAS_ELEMS) {
        int h = id / (NT * NT), nm = id - h * (NT * NT);
        g_bias[id] = table[rel[nm] * NH + h];
    }
    if (id < NQKV * 96) {
        int n = id / 96, k = (id % 96) * 2;
        split2(w_qkv[k * NQKV + n], w_qkv[(k + 1) * NQKV + n],
               g_wq_hi[bpk_idx(n, k)], g_wq_lo[bpk_idx(n, k)]);
    }
    if (id < DIMM * 96) {
        int n = id / 96, k = (id % 96) * 2;
        split2(w_out[k * DIMM + n], w_out[(k + 1) * DIMM + n],
               g_wo_hi[bpk_idx(n, k)], g_wo_lo[bpk_idx(n, k)]);
    }
}

// ---------------- pack activations ----------------
template <int SRC>
__global__ void pack_a_kernel(const float* __restrict__ x) {
    int id = blockIdx.x * 256 + threadIdx.x;
    int m = id / 96, k = (id % 96) * 2;
    const float* src = (SRC == 0) ? x : g_ctx;
    float2 v = *(const float2*)&src[(size_t)m * DIMM + k];
    int idx = apk_idx(m, k);
    if (SRC == 0) split2(v.x, v.y, g_xpk_hi[idx], g_xpk_lo[idx]);
    else          split2(v.x, v.y, g_cpk_hi[idx], g_cpk_lo[idx]);
}

// ---------------- bf16-split tensor GEMM (unchanged, R11-verified) ----------------
template <int EPI>
__global__ __launch_bounds__(256)
void gemm_mma(const float* __restrict__ bias, float* __restrict__ C) {
    extern __shared__ uint4 smem4[];
    uint4* Asm = smem4;
    uint4* Bsm = smem4 + 2048;

    const int tid = threadIdx.x, lane = tid & 31, wid = tid >> 5;
    const int wm = wid >> 1, wn = wid & 1;
    const int m0t = blockIdx.y * 8;
    const int block = blockIdx.x;

    const uint4* Ahi = (const uint4*)((EPI == 0) ? g_xpk_hi : g_cpk_hi);
    const uint4* Alo = (const uint4*)((EPI == 0) ? g_xpk_lo : g_cpk_lo);
    const uint4* Bhi = (const uint4*)((EPI == 0) ? g_wq_hi  : g_wo_hi);
    const uint4* Blo = (const uint4*)((EPI == 0) ? g_wq_lo  : g_wo_lo);

    float acc[2][4][4];
#pragma unroll
    for (int mt = 0; mt < 2; mt++)
#pragma unroll
        for (int nt = 0; nt < 4; nt++)
#pragma unroll
            for (int r = 0; r < 4; r++) acc[mt][nt][r] = 0.f;

    auto a_gidx = [&](int u, int c) {
        int mt = (u & 511) >> 6, j = (u >> 5) & 1, q = u & 31;
        return ((m0t + mt) * KSTEPS + 2 * c + j) * 32 + q;
    };
    auto b_gidx = [&](int u, int c) {
        int j = (u >> 7) & 1, nt = (u >> 4) & 7, q = u & 15;
        return ((block * KSTEPS + 2 * c + j) * 8 + nt) * 16 + q;
    };

#pragma unroll
    for (int i = 0; i < 4; i++) {
        int u = tid + 256 * i;
        Asm[u] = (u < 512 ? Ahi : Alo)[a_gidx(u, 0)];
    }
#pragma unroll
    for (int i = 0; i < 2; i++) {
        int u = tid + 256 * i;
        Bsm[u] = (u < 256 ? Bhi : Blo)[b_gidx(u, 0)];
    }
    __syncthreads();

    uint4 pa[4], pb[2];
#pragma unroll 1
    for (int c = 0; c < 6; c++) {
        const int s = c & 1;
        if (c < 5) {
#pragma unroll
            for (int i = 0; i < 4; i++) {
                int u = tid + 256 * i;
                pa[i] = (u < 512 ? Ahi : Alo)[a_gidx(u, c + 1)];
            }
#pragma unroll
            for (int i = 0; i < 2; i++) {
                int u = tid + 256 * i;
                pb[i] = (u < 256 ? Bhi : Blo)[b_gidx(u, c + 1)];
            }
        }
        const uint4* As = Asm + s * 1024;
        const uint2* Bs2 = (const uint2*)(Bsm + s * 512);
#pragma unroll
        for (int j = 0; j < 2; j++) {
            uint4 ah[2], al[2];
#pragma unroll
            for (int mt = 0; mt < 2; mt++) {
                ah[mt] = As[(wm * 2 + mt) * 64 + j * 32 + lane];
                al[mt] = As[512 + (wm * 2 + mt) * 64 + j * 32 + lane];
            }
            uint2 bh[4], bl[4];
#pragma unroll
            for (int nt = 0; nt < 4; nt++) {
                bh[nt] = Bs2[(j * 8 + wn * 4 + nt) * 32 + lane];
                bl[nt] = Bs2[512 + (j * 8 + wn * 4 + nt) * 32 + lane];
            }
#pragma unroll
            for (int mt = 0; mt < 2; mt++)
#pragma unroll
                for (int nt = 0; nt < 4; nt++) {
                    mma_bf16(acc[mt][nt], (const uint32_t*)&ah[mt], (const uint32_t*)&bh[nt]);
                    mma_bf16(acc[mt][nt], (const uint32_t*)&ah[mt], (const uint32_t*)&bl[nt]);
                    mma_bf16(acc[mt][nt], (const uint32_t*)&al[mt], (const uint32_t*)&bh[nt]);
                }
        }
        if (c < 5) {
            uint4* Ad = Asm + (s ^ 1) * 1024;
            uint4* Bd = Bsm + (s ^ 1) * 512;
#pragma unroll
            for (int i = 0; i < 4; i++) Ad[tid + 256 * i] = pa[i];
#pragma unroll
            for (int i = 0; i < 2; i++) Bd[tid + 256 * i] = pb[i];
        }
        __syncthreads();
    }

    const int g = lane >> 2, t = lane & 3;
#pragma unroll
    for (int mt = 0; mt < 2; mt++) {
        const int r0 = m0t * 16 + wm * 32 + mt * 16 + g;
#pragma unroll
        for (int nt = 0; nt < 4; nt++) {
            const int cn = wn * 32 + nt * 8 + 2 * t;
            const float2 bi = *(const float2*)&bias[block * 64 + cn];
            float2 v0 = make_float2(acc[mt][nt][0] + bi.x, acc[mt][nt][1] + bi.y);
            float2 v1 = make_float2(acc[mt][nt][2] + bi.x, acc[mt][nt][3] + bi.y);
            if (EPI == 0) {
                const int comp = block / 3;
                const int n = (block % 3) * 64 + cn;
                const int h = n >> 5, d = n & 31;
                float* dst = (comp == 0) ? g_q : (comp == 1 ? g_k : g_v);
                if (comp == 0) { v0.x *= QSCALE; v0.y *= QSCALE; v1.x *= QSCALE; v1.y *= QSCALE; }
                int w0 = r0 / NT, tok0 = r0 - w0 * NT;
                int r1 = r0 + 8, w1 = r1 / NT, tok1 = r1 - w1 * NT;
                *(float2*)&dst[(((w0 * NH + h) * NT + tok0) << 5) + d] = v0;
                *(float2*)&dst[(((w1 * NH + h) * NT + tok1) << 5) + d] = v1;
            } else {
                *(float2*)&C[(size_t)r0 * DIMM + block * 64 + cn] = v0;
                *(float2*)&C[(size_t)(r0 + 8) * DIMM + block * 64 + cn] = v1;
            }
        }
    }
}

// ---------------- attention on mma: one CTA per (w,h), 9 warps ----------------
// smem: q/k/v bf16-split fragments, 6 x 2304 u32 = 55,296 B
__global__ __launch_bounds__(288, 2)
void attn_kernel(const int* __restrict__ mask) {
    extern __shared__ uint32_t smu[];
    uint32_t* q_hi = smu;
    uint32_t* q_lo = smu + 2304;
    uint32_t* k_hi = smu + 4608;
    uint32_t* k_lo = smu + 6912;
    uint32_t* v_hi = smu + 9216;
    uint32_t* v_lo = smu + 11520;

    const int wh = blockIdx.x;
    const int h = wh % NH, w = wh / NH;
    const int tid = threadIdx.x, lane = tid & 31, wm = tid >> 5;
    const int base = ((w * NH + h) * NT) << 5;

    // ---- convert q/k/v into fragment-packed bf16-split smem ----
    for (int p = tid; p < 2304; p += 288) {   // q: A-frag [mt][ks][lane][reg]
        int mt = p >> 8, ks = (p >> 7) & 1, ln = (p >> 2) & 31, rg = p & 3;
        int row = mt * 16 + (ln >> 2) + 8 * (rg & 1);
        int col = ks * 16 + 2 * (ln & 3) + 8 * (rg >> 1);
        float2 v2 = *(const float2*)&g_q[base + row * 32 + col];
        split2(v2.x, v2.y, q_hi[p], q_lo[p]);
    }
    for (int p = tid; p < 2304; p += 288) {   // k: B-frag n=token,k=d
        int nt = p >> 7, ks = (p >> 6) & 1, ln = (p >> 1) & 31, rg = p & 1;
        int tok = nt * 8 + (ln >> 2);
        int d   = ks * 16 + 2 * (ln & 3) + 8 * rg;
        float2 v2 = *(const float2*)&g_k[base + tok * 32 + d];
        split2(v2.x, v2.y, k_hi[p], k_lo[p]);
    }
    for (int p = tid; p < 2304; p += 288) {   // v: B-frag n=d,k=token
        int rest = p >> 6, ln = (p >> 1) & 31, rg = p & 1;
        int nt = rest / 9, ks = rest - nt * 9;
        int d   = nt * 8 + (ln >> 2);
        int tok = ks * 16 + 2 * (ln & 3) + 8 * rg;
        float va = g_v[base + tok * 32 + d];
        float vb = g_v[base + (tok + 1) * 32 + d];
        split2(va, vb, v_hi[p], v_lo[p]);
    }
    __syncthreads();

    // ---- QK^T: warp wm -> rows [wm*16, wm*16+16), 18 n-tiles ----
    float acc[18][4];
#pragma unroll
    for (int nt = 0; nt < 18; nt++)
#pragma unroll
        for (int r = 0; r < 4; r++) acc[nt][r] = 0.f;

    uint4 qa_h[2], qa_l[2];
#pragma unroll
    for (int ks = 0; ks < 2; ks++) {
        qa_h[ks] = *(const uint4*)&q_hi[(wm * 2 + ks) * 128 + lane * 4];
        qa_l[ks] = *(const uint4*)&q_lo[(wm * 2 + ks) * 128 + lane * 4];
    }
#pragma unroll
    for (int ks = 0; ks < 2; ks++) {
#pragma unroll
        for (int nt = 0; nt < 18; nt++) {
            uint2 bh = *(const uint2*)&k_hi[(nt * 2 + ks) * 64 + lane * 2];
            uint2 bl = *(const uint2*)&k_lo[(nt * 2 + ks) * 64 + lane * 2];
            mma_bf16(acc[nt], (const uint32_t*)&qa_h[ks], (const uint32_t*)&bh);
            mma_bf16(acc[nt], (const uint32_t*)&qa_h[ks], (const uint32_t*)&bl);
            mma_bf16(acc[nt], (const uint32_t*)&qa_l[ks], (const uint32_t*)&bh);
        }
    }

    // ---- bias + mask + softmax in accumulator layout ----
    const int g = lane >> 2, t = lane & 3;
    const int rA = wm * 16 + g, rB = rA + 8;
    {
        const float* bb = g_bias + h * NT * NT;
        const int*   mm = mask + (size_t)w * NT * NT;
#pragma unroll
        for (int nt = 0; nt < 18; nt++) {
            const int cn = nt * 8 + 2 * t;
            float2 bA = *(const float2*)&bb[rA * NT + cn];
            float2 bB = *(const float2*)&bb[rB * NT + cn];
            int2   mA = *(const int2*)&mm[rA * NT + cn];
            int2   mB = *(const int2*)&mm[rB * NT + cn];
            acc[nt][0] = (mA.x != 0) ? acc[nt][0] + bA.x : -1.0e9f;
            acc[nt][1] = (mA.y != 0) ? acc[nt][1] + bA.y : -1.0e9f;
            acc[nt][2] = (mB.x != 0) ? acc[nt][2] + bB.x : -1.0e9f;
            acc[nt][3] = (mB.y != 0) ? acc[nt][3] + bB.y : -1.0e9f;
        }
        float mxA = -3.0e38f, mxB = -3.0e38f;
#pragma unroll
        for (int nt = 0; nt < 18; nt++) {
            mxA = fmaxf(mxA, fmaxf(acc[nt][0], acc[nt][1]));
            mxB = fmaxf(mxB, fmaxf(acc[nt][2], acc[nt][3]));
        }
#pragma unroll
        for (int o = 1; o <= 2; o <<= 1) {
            mxA = fmaxf(mxA, __shfl_xor_sync(0xffffffffu, mxA, o));
            mxB = fmaxf(mxB, __shfl_xor_sync(0xffffffffu, mxB, o));
        }
        float sA = 0.f, sB = 0.f;
#pragma unroll
        for (int nt = 0; nt < 18; nt++) {
            acc[nt][0] = __expf(acc[nt][0] - mxA); sA += acc[nt][0];
            acc[nt][1] = __expf(acc[nt][1] - mxA); sA += acc[nt][1];
            acc[nt][2] = __expf(acc[nt][2] - mxB); sB += acc[nt][2];
            acc[nt][3] = __expf(acc[nt][3] - mxB); sB += acc[nt][3];
        }
#pragma unroll
        for (int o = 1; o <= 2; o <<= 1) {
            sA += __shfl_xor_sync(0xffffffffu, sA, o);
            sB += __shfl_xor_sync(0xffffffffu, sB, o);
        }
        const float iA = 1.f / sA, iB = 1.f / sB;
#pragma unroll
        for (int nt = 0; nt < 18; nt++) {
            acc[nt][0] *= iA; acc[nt][1] *= iA;
            acc[nt][2] *= iB; acc[nt][3] *= iB;
        }
    }

    // ---- PV: P accum pairs -> A-frags in-register; V B-frags from smem ----
    float o4[4][4];
#pragma unroll
    for (int nt = 0; nt < 4; nt++)
#pragma unroll
        for (int r = 0; r < 4; r++) o4[nt][r] = 0.f;

#pragma unroll
    for (int kt = 0; kt < 9; kt++) {
        uint32_t ah[4], al[4];
        split2(acc[2 * kt][0],     acc[2 * kt][1],     ah[0], al[0]);
        split2(acc[2 * kt][2],     acc[2 * kt][3],     ah[1], al[1]);
        split2(acc[2 * kt + 1][0], acc[2 * kt + 1][1], ah[2], al[2]);
        split2(acc[2 * kt + 1][2], acc[2 * kt + 1][3], ah[3], al[3]);
#pragma unroll
        for (int nt = 0; nt < 4; nt++) {
            uint2 bh = *(const uint2*)&v_hi[((nt * 9 + kt) * 32 + lane) * 2];
            uint2 bl = *(const uint2*)&v_lo[((nt * 9 + kt) * 32 + lane) * 2];
            mma_bf16(o4[nt], ah, (const uint32_t*)&bh);
            mma_bf16(o4[nt], ah, (const uint32_t*)&bl);
            mma_bf16(o4[nt], al, (const uint32_t*)&bh);
        }
    }

    // ---- write ctx ----
#pragma unroll
    for (int nt = 0; nt < 4; nt++) {
        const int cn = h * HD + nt * 8 + 2 * t;
        *(float2*)&g_ctx[(w * NT + rA) * DIMM + cn] = make_float2(o4[nt][0], o4[nt][1]);
        *(float2*)&g_ctx[(w * NT + rB) * DIMM + cn] = make_float2(o4[nt][2], o4[nt][3]);
    }
}

// ---------------- launch ----------------
extern "C" void kernel_launch(void* const* d_in, const int* in_sizes, int n_in,
                              void* d_out, int out_size) {
    const float* x     = (const float*)d_in[0];
    const int*   mask  = (const int*)  d_in[1];
    const int*   rel   = (const int*)  d_in[2];
    const float* w_qkv = (const float*)d_in[3];
    const float* b_qkv = (const float*)d_in[4];
    const float* w_out = (const float*)d_in[5];
    const float* b_out = (const float*)d_in[6];
    const float* btab  = (const float*)d_in[7];
    float*       out   = (float*)d_out;

    cudaStream_t stream = cudaStreamLegacy;
    cudaStreamCaptureStatus st = cudaStreamCaptureStatusNone;
    if (cudaStreamIsCapturing(cudaStreamPerThread, &st) == cudaSuccess &&
        st == cudaStreamCaptureStatusActive) {
        stream = cudaStreamPerThread;
    }

    const int ATTN_SMEM = 13824 * 4;   // 55296
    const int GEMM_SMEM = 49152;
    cudaFuncSetAttribute(attn_kernel,
                         cudaFuncAttributeMaxDynamicSharedMemorySize, ATTN_SMEM);
    cudaFuncSetAttribute(gemm_mma<0>,
                         cudaFuncAttributeMaxDynamicSharedMemorySize, GEMM_SMEM);
    cudaFuncSetAttribute(gemm_mma<1>,
                         cudaFuncAttributeMaxDynamicSharedMemorySize, GEMM_SMEM);

    prep_kernel<<<(BIAS_ELEMS + 255) / 256, 256, 0, stream>>>(rel, btab, w_qkv, w_out);
    pack_a_kernel<0><<<A_PK / 256, 256, 0, stream>>>(x);

    {
        dim3 grid(9, MROWS / 128);
        gemm_mma<0><<<grid, 256, GEMM_SMEM, stream>>>(b_qkv, nullptr);
    }

    attn_kernel<<<NW * NH, 288, ATTN_SMEM, stream>>>(mask);

    pack_a_kernel<1><<<A_PK / 256, 256, 0, stream>>>(nullptr);
    {
        dim3 grid(3, MROWS / 128);
        gemm_mma<1><<<grid, 256, GEMM_SMEM, stream>>>(b_out, out);
    }
}

// round 13
// speedup vs baseline: 4.2304x; 1.0582x over previous
#include <cuda_runtime.h>
#include <cuda_bf16.h>
#include <cstdint>

#define NW   960
#define NT   144
#define DIMM 192
#define NH   6
#define HD   32
#define NQKV 576
#define MROWS (NW*NT)
#define QSCALE 0.17677669529663689f
#define BIAS_ELEMS (NH*NT*NT)
#define MT16  (MROWS/16)
#define KSTEPS 12
#define A_PK  (MT16*KSTEPS*128)
#define HPK   (NW*NH*2304)          // per-head packed words (q or k)

__device__ float g_ctx[MROWS*DIMM];
__device__ float g_bias[BIAS_ELEMS];
__device__ float g_vT[NW*NH*HD*NT];           // v transposed [w][h][d][tok]
__device__ uint32_t g_qpk_hi[HPK], g_qpk_lo[HPK];
__device__ uint32_t g_kpk_hi[HPK], g_kpk_lo[HPK];
__device__ uint32_t g_xpk_hi[A_PK], g_xpk_lo[A_PK];
__device__ uint32_t g_cpk_hi[A_PK], g_cpk_lo[A_PK];
__device__ uint32_t g_wq_hi[9*12*512],  g_wq_lo[9*12*512];
__device__ uint32_t g_wo_hi[3*12*512],  g_wo_lo[3*12*512];

__device__ __forceinline__ uint32_t bfpack(float a, float b) {
    __nv_bfloat162 t = __floats2bfloat162_rn(a, b);
    return *reinterpret_cast<uint32_t*>(&t);
}
__device__ __forceinline__ void split2(float a, float b, uint32_t& hi, uint32_t& lo) {
    hi = bfpack(a, b);
    __nv_bfloat162 h = *reinterpret_cast<__nv_bfloat162*>(&hi);
    lo = bfpack(a - __bfloat162float(h.x), b - __bfloat162float(h.y));
}
__device__ __forceinline__ void mma_bf16(float* d, const uint32_t* a, const uint32_t* b) {
    asm volatile("mma.sync.aligned.m16n8k16.row.col.f32.bf16.bf16.f32 "
        "{%0,%1,%2,%3}, {%4,%5,%6,%7}, {%8,%9}, {%0,%1,%2,%3};"
        : "+f"(d[0]), "+f"(d[1]), "+f"(d[2]), "+f"(d[3])
        : "r"(a[0]), "r"(a[1]), "r"(a[2]), "r"(a[3]), "r"(b[0]), "r"(b[1]));
}

__device__ __forceinline__ int apk_idx(int m, int k) {
    int mtile = m >> 4, mr = m & 15, kstep = k >> 4, kk = k & 15;
    int lane = (mr & 7) * 4 + ((kk & 7) >> 1);
    int reg  = ((mr >> 3) & 1) + ((kk >> 3) << 1);
    return ((mtile * KSTEPS + kstep) * 32 + lane) * 4 + reg;
}
__device__ __forceinline__ int bpk_idx(int n, int k) {
    int block = n >> 6, nl = n & 63, ntile = nl >> 3, g = nl & 7;
    int kstep = k >> 4, kk = k & 15;
    int lane = g * 4 + ((kk & 7) >> 1);
    int reg  = (kk >> 3) & 1;
    return ((block * KSTEPS + kstep) * 8 + ntile) * 64 + lane * 2 + reg;
}

// ---------------- prep: bias expand + weight packs ----------------
__global__ void prep_kernel(const int* __restrict__ rel, const float* __restrict__ table,
                            const float* __restrict__ w_qkv, const float* __restrict__ w_out) {
    int id = blockIdx.x * 256 + threadIdx.x;
    if (id < BIAS_ELEMS) {
        int h = id / (NT * NT), nm = id - h * (NT * NT);
        g_bias[id] = table[rel[nm] * NH + h];
    }
    if (id < NQKV * 96) {
        int n = id / 96, k = (id % 96) * 2;
        split2(w_qkv[k * NQKV + n], w_qkv[(k + 1) * NQKV + n],
               g_wq_hi[bpk_idx(n, k)], g_wq_lo[bpk_idx(n, k)]);
    }
    if (id < DIMM * 96) {
        int n = id / 96, k = (id % 96) * 2;
        split2(w_out[k * DIMM + n], w_out[(k + 1) * DIMM + n],
               g_wo_hi[bpk_idx(n, k)], g_wo_lo[bpk_idx(n, k)]);
    }
}

// ---------------- pack activations ----------------
template <int SRC>
__global__ void pack_a_kernel(const float* __restrict__ x) {
    int id = blockIdx.x * 256 + threadIdx.x;
    int m = id / 96, k = (id % 96) * 2;
    const float* src = (SRC == 0) ? x : g_ctx;
    float2 v = *(const float2*)&src[(size_t)m * DIMM + k];
    int idx = apk_idx(m, k);
    if (SRC == 0) split2(v.x, v.y, g_xpk_hi[idx], g_xpk_lo[idx]);
    else          split2(v.x, v.y, g_cpk_hi[idx], g_cpk_lo[idx]);
}

// ---------------- bf16-split tensor GEMM ----------------
// EPI==0: QKV; epilogue emits q/k fragment-packed bf16 split + vT fp32.
// EPI==1: out-proj, dense C.
template <int EPI>
__global__ __launch_bounds__(256)
void gemm_mma(const float* __restrict__ bias, float* __restrict__ C) {
    extern __shared__ uint4 smem4[];
    uint4* Asm = smem4;
    uint4* Bsm = smem4 + 2048;

    const int tid = threadIdx.x, lane = tid & 31, wid = tid >> 5;
    const int wm = wid >> 1, wn = wid & 1;
    const int m0t = blockIdx.y * 8;
    const int block = blockIdx.x;

    const uint4* Ahi = (const uint4*)((EPI == 0) ? g_xpk_hi : g_cpk_hi);
    const uint4* Alo = (const uint4*)((EPI == 0) ? g_xpk_lo : g_cpk_lo);
    const uint4* Bhi = (const uint4*)((EPI == 0) ? g_wq_hi  : g_wo_hi);
    const uint4* Blo = (const uint4*)((EPI == 0) ? g_wq_lo  : g_wo_lo);

    float acc[2][4][4];
#pragma unroll
    for (int mt = 0; mt < 2; mt++)
#pragma unroll
        for (int nt = 0; nt < 4; nt++)
#pragma unroll
            for (int r = 0; r < 4; r++) acc[mt][nt][r] = 0.f;

    auto a_gidx = [&](int u, int c) {
        int mt = (u & 511) >> 6, j = (u >> 5) & 1, q = u & 31;
        return ((m0t + mt) * KSTEPS + 2 * c + j) * 32 + q;
    };
    auto b_gidx = [&](int u, int c) {
        int j = (u >> 7) & 1, nt = (u >> 4) & 7, q = u & 15;
        return ((block * KSTEPS + 2 * c + j) * 8 + nt) * 16 + q;
    };

#pragma unroll
    for (int i = 0; i < 4; i++) {
        int u = tid + 256 * i;
        Asm[u] = (u < 512 ? Ahi : Alo)[a_gidx(u, 0)];
    }
#pragma unroll
    for (int i = 0; i < 2; i++) {
        int u = tid + 256 * i;
        Bsm[u] = (u < 256 ? Bhi : Blo)[b_gidx(u, 0)];
    }
    __syncthreads();

    uint4 pa[4], pb[2];
#pragma unroll 1
    for (int c = 0; c < 6; c++) {
        const int s = c & 1;
        if (c < 5) {
#pragma unroll
            for (int i = 0; i < 4; i++) {
                int u = tid + 256 * i;
                pa[i] = (u < 512 ? Ahi : Alo)[a_gidx(u, c + 1)];
            }
#pragma unroll
            for (int i = 0; i < 2; i++) {
                int u = tid + 256 * i;
                pb[i] = (u < 256 ? Bhi : Blo)[b_gidx(u, c + 1)];
            }
        }
        const uint4* As = Asm + s * 1024;
        const uint2* Bs2 = (const uint2*)(Bsm + s * 512);
#pragma unroll
        for (int j = 0; j < 2; j++) {
            uint4 ah[2], al[2];
#pragma unroll
            for (int mt = 0; mt < 2; mt++) {
                ah[mt] = As[(wm * 2 + mt) * 64 + j * 32 + lane];
                al[mt] = As[512 + (wm * 2 + mt) * 64 + j * 32 + lane];
            }
            uint2 bh[4], bl[4];
#pragma unroll
            for (int nt = 0; nt < 4; nt++) {
                bh[nt] = Bs2[(j * 8 + wn * 4 + nt) * 32 + lane];
                bl[nt] = Bs2[512 + (j * 8 + wn * 4 + nt) * 32 + lane];
            }
#pragma unroll
            for (int mt = 0; mt < 2; mt++)
#pragma unroll
                for (int nt = 0; nt < 4; nt++) {
                    mma_bf16(acc[mt][nt], (const uint32_t*)&ah[mt], (const uint32_t*)&bh[nt]);
                    mma_bf16(acc[mt][nt], (const uint32_t*)&ah[mt], (const uint32_t*)&bl[nt]);
                    mma_bf16(acc[mt][nt], (const uint32_t*)&al[mt], (const uint32_t*)&bh[nt]);
                }
        }
        if (c < 5) {
            uint4* Ad = Asm + (s ^ 1) * 1024;
            uint4* Bd = Bsm + (s ^ 1) * 512;
#pragma unroll
            for (int i = 0; i < 4; i++) Ad[tid + 256 * i] = pa[i];
#pragma unroll
            for (int i = 0; i < 2; i++) Bd[tid + 256 * i] = pb[i];
        }
        __syncthreads();
    }

    const int g = lane >> 2, t = lane & 3;
#pragma unroll
    for (int mt = 0; mt < 2; mt++) {
        const int r0 = m0t * 16 + wm * 32 + mt * 16 + g;
#pragma unroll
        for (int nt = 0; nt < 4; nt++) {
            const int cn = wn * 32 + nt * 8 + 2 * t;
            const float2 bi = *(const float2*)&bias[block * 64 + cn];
            float2 v0 = make_float2(acc[mt][nt][0] + bi.x, acc[mt][nt][1] + bi.y);
            float2 v1 = make_float2(acc[mt][nt][2] + bi.x, acc[mt][nt][3] + bi.y);
            if (EPI == 0) {
                const int comp = block / 3;
                const int n = (block % 3) * 64 + cn;   // 0..191
                const int h = n >> 5, d = n & 31;      // d even
                const int ks = d >> 4, kk = d & 15;
                const int w0 = r0 / NT, tok0 = r0 - w0 * NT;
                const int tok1 = tok0 + 8;             // same window (16-row tile)
                const size_t hb = (size_t)(w0 * NH + h);
                if (comp == 0) {                        // q -> A-frag pack, scaled
                    v0.x *= QSCALE; v0.y *= QSCALE; v1.x *= QSCALE; v1.y *= QSCALE;
                    const int mt9 = tok0 >> 4;
                    const int ln = ((tok0 & 7) * 4) + ((kk & 7) >> 1);
                    const int rbase = ((kk >> 3) & 1) << 1;
                    const size_t ib = ((hb * 9 + mt9) * 2 + ks) * 128 + ln * 4;
                    uint32_t hi0, lo0, hi1, lo1;
                    split2(v0.x, v0.y, hi0, lo0);       // row tok0: reg bit0 = 0
                    split2(v1.x, v1.y, hi1, lo1);       // row tok1: reg bit0 = 1
                    g_qpk_hi[ib + rbase]     = hi0; g_qpk_lo[ib + rbase]     = lo0;
                    g_qpk_hi[ib + rbase + 1] = hi1; g_qpk_lo[ib + rbase + 1] = lo1;
                } else if (comp == 1) {                 // k -> B-frag pack
                    const int rg = (kk >> 3) & 1;
                    const int lk = (kk & 7) >> 1;
                    const size_t kb = hb * 2304;
                    {
                        const int ntk = tok0 >> 3, ln = (tok0 & 7) * 4 + lk;
                        uint32_t hi, lo; split2(v0.x, v0.y, hi, lo);
                        const size_t ix = kb + (ntk * 2 + ks) * 64 + ln * 2 + rg;
                        g_kpk_hi[ix] = hi; g_kpk_lo[ix] = lo;
                    }
                    {
                        const int ntk = tok1 >> 3, ln = (tok1 & 7) * 4 + lk;
                        uint32_t hi, lo; split2(v1.x, v1.y, hi, lo);
                        const size_t ix = kb + (ntk * 2 + ks) * 64 + ln * 2 + rg;
                        g_kpk_hi[ix] = hi; g_kpk_lo[ix] = lo;
                    }
                } else {                                // v -> fp32 transposed
                    float* vt = g_vT + hb * HD * NT;
                    vt[d * NT + tok0]       = v0.x;
                    vt[(d + 1) * NT + tok0] = v0.y;
                    vt[d * NT + tok1]       = v1.x;
                    vt[(d + 1) * NT + tok1] = v1.y;
                }
            } else {
                *(float2*)&C[(size_t)r0 * DIMM + block * 64 + cn] = v0;
                *(float2*)&C[(size_t)(r0 + 8) * DIMM + block * 64 + cn] = v1;
            }
        }
    }
}

// ---------------- attention: one CTA per (w,h), 9 warps, frags from gmem ----------------
__global__ __launch_bounds__(288, 2)
void attn_kernel(const int* __restrict__ mask) {
    __shared__ uint32_t v_hi[2304], v_lo[2304];

    const int wh = blockIdx.x;
    const int h = wh % NH, w = wh / NH;
    const int tid = threadIdx.x, lane = tid & 31, wm = tid >> 5;
    const size_t hb = (size_t)(w * NH + h);

    // ---- v conversion (contiguous float2 from vT); latency hidden by QK below ----
    const float* vt = g_vT + hb * HD * NT;
#pragma unroll
    for (int it = 0; it < 8; it++) {
        int p = tid + 288 * it;
        int rest = p >> 6, ln = (p >> 1) & 31, rg = p & 1;
        int nt = rest / 9, kt = rest - nt * 9;
        int d = nt * 8 + (ln >> 2);
        int tok = kt * 16 + 2 * (ln & 3) + 8 * rg;
        float2 vv = *(const float2*)&vt[d * NT + tok];
        split2(vv.x, vv.y, v_hi[p], v_lo[p]);
    }

    // ---- QK^T: q frags direct LDG.128; k frags direct LDG.64 (L1-shared) ----
    float acc[18][4];
#pragma unroll
    for (int nt = 0; nt < 18; nt++)
#pragma unroll
        for (int r = 0; r < 4; r++) acc[nt][r] = 0.f;

    const uint32_t* qh = g_qpk_hi + (hb * 9 + wm) * 256;
    const uint32_t* ql = g_qpk_lo + (hb * 9 + wm) * 256;
    uint4 qa_h[2], qa_l[2];
#pragma unroll
    for (int ks = 0; ks < 2; ks++) {
        qa_h[ks] = *(const uint4*)&qh[ks * 128 + lane * 4];
        qa_l[ks] = *(const uint4*)&ql[ks * 128 + lane * 4];
    }
    const uint32_t* kh = g_kpk_hi + hb * 2304;
    const uint32_t* kl = g_kpk_lo + hb * 2304;
#pragma unroll
    for (int ks = 0; ks < 2; ks++) {
#pragma unroll
        for (int nt = 0; nt < 18; nt++) {
            uint2 bh = *(const uint2*)&kh[(nt * 2 + ks) * 64 + lane * 2];
            uint2 bl = *(const uint2*)&kl[(nt * 2 + ks) * 64 + lane * 2];
            mma_bf16(acc[nt], (const uint32_t*)&qa_h[ks], (const uint32_t*)&bh);
            mma_bf16(acc[nt], (const uint32_t*)&qa_h[ks], (const uint32_t*)&bl);
            mma_bf16(acc[nt], (const uint32_t*)&qa_l[ks], (const uint32_t*)&bh);
        }
    }

    // ---- bias + mask + softmax in accumulator layout ----
    const int g = lane >> 2, t = lane & 3;
    const int rA = wm * 16 + g, rB = rA + 8;
    {
        const float* bb = g_bias + h * NT * NT;
        const int*   mm = mask + (size_t)w * NT * NT;
#pragma unroll
        for (int nt = 0; nt < 18; nt++) {
            const int cn = nt * 8 + 2 * t;
            float2 bA = *(const float2*)&bb[rA * NT + cn];
            float2 bB = *(const float2*)&bb[rB * NT + cn];
            int2   mA = *(const int2*)&mm[rA * NT + cn];
            int2   mB = *(const int2*)&mm[rB * NT + cn];
            acc[nt][0] = (mA.x != 0) ? acc[nt][0] + bA.x : -1.0e9f;
            acc[nt][1] = (mA.y != 0) ? acc[nt][1] + bA.y : -1.0e9f;
            acc[nt][2] = (mB.x != 0) ? acc[nt][2] + bB.x : -1.0e9f;
            acc[nt][3] = (mB.y != 0) ? acc[nt][3] + bB.y : -1.0e9f;
        }
        float mxA = -3.0e38f, mxB = -3.0e38f;
#pragma unroll
        for (int nt = 0; nt < 18; nt++) {
            mxA = fmaxf(mxA, fmaxf(acc[nt][0], acc[nt][1]));
            mxB = fmaxf(mxB, fmaxf(acc[nt][2], acc[nt][3]));
        }
#pragma unroll
        for (int o = 1; o <= 2; o <<= 1) {
            mxA = fmaxf(mxA, __shfl_xor_sync(0xffffffffu, mxA, o));
            mxB = fmaxf(mxB, __shfl_xor_sync(0xffffffffu, mxB, o));
        }
        float sA = 0.f, sB = 0.f;
#pragma unroll
        for (int nt = 0; nt < 18; nt++) {
            acc[nt][0] = __expf(acc[nt][0] - mxA); sA += acc[nt][0];
            acc[nt][1] = __expf(acc[nt][1] - mxA); sA += acc[nt][1];
            acc[nt][2] = __expf(acc[nt][2] - mxB); sB += acc[nt][2];
            acc[nt][3] = __expf(acc[nt][3] - mxB); sB += acc[nt][3];
        }
#pragma unroll
        for (int o = 1; o <= 2; o <<= 1) {
            sA += __shfl_xor_sync(0xffffffffu, sA, o);
            sB += __shfl_xor_sync(0xffffffffu, sB, o);
        }
        const float iA = 1.f / sA, iB = 1.f / sB;
#pragma unroll
        for (int nt = 0; nt < 18; nt++) {
            acc[nt][0] *= iA; acc[nt][1] *= iA;
            acc[nt][2] *= iB; acc[nt][3] *= iB;
        }
    }

    __syncthreads();   // v frags ready in smem

    // ---- PV: P accum pairs -> A-frags in-register; V B-frags from smem ----
    float o4[4][4];
#pragma unroll
    for (int nt = 0; nt < 4; nt++)
#pragma unroll
        for (int r = 0; r < 4; r++) o4[nt][r] = 0.f;

#pragma unroll
    for (int kt = 0; kt < 9; kt++) {
        uint32_t ah[4], al[4];
        split2(acc[2 * kt][0],     acc[2 * kt][1],     ah[0], al[0]);
        split2(acc[2 * kt][2],     acc[2 * kt][3],     ah[1], al[1]);
        split2(acc[2 * kt + 1][0], acc[2 * kt + 1][1], ah[2], al[2]);
        split2(acc[2 * kt + 1][2], acc[2 * kt + 1][3], ah[3], al[3]);
#pragma unroll
        for (int nt = 0; nt < 4; nt++) {
            uint2 bh = *(const uint2*)&v_hi[((nt * 9 + kt) * 32 + lane) * 2];
            uint2 bl = *(const uint2*)&v_lo[((nt * 9 + kt) * 32 + lane) * 2];
            mma_bf16(o4[nt], ah, (const uint32_t*)&bh);
            mma_bf16(o4[nt], ah, (const uint32_t*)&bl);
            mma_bf16(o4[nt], al, (const uint32_t*)&bh);
        }
    }

    // ---- write ctx ----
#pragma unroll
    for (int nt = 0; nt < 4; nt++) {
        const int cn = h * HD + nt * 8 + 2 * t;
        *(float2*)&g_ctx[(w * NT + rA) * DIMM + cn] = make_float2(o4[nt][0], o4[nt][1]);
        *(float2*)&g_ctx[(w * NT + rB) * DIMM + cn] = make_float2(o4[nt][2], o4[nt][3]);
    }
}

// ---------------- launch ----------------
extern "C" void kernel_launch(void* const* d_in, const int* in_sizes, int n_in,
                              void* d_out, int out_size) {
    const float* x     = (const float*)d_in[0];
    const int*   mask  = (const int*)  d_in[1];
    const int*   rel   = (const int*)  d_in[2];
    const float* w_qkv = (const float*)d_in[3];
    const float* b_qkv = (const float*)d_in[4];
    const float* w_out = (const float*)d_in[5];
    const float* b_out = (const float*)d_in[6];
    const float* btab  = (const float*)d_in[7];
    float*       out   = (float*)d_out;

    cudaStream_t stream = cudaStreamLegacy;
    cudaStreamCaptureStatus st = cudaStreamCaptureStatusNone;
    if (cudaStreamIsCapturing(cudaStreamPerThread, &st) == cudaSuccess &&
        st == cudaStreamCaptureStatusActive) {
        stream = cudaStreamPerThread;
    }

    const int GEMM_SMEM = 49152;
    cudaFuncSetAttribute(gemm_mma<0>,
                         cudaFuncAttributeMaxDynamicSharedMemorySize, GEMM_SMEM);
    cudaFuncSetAttribute(gemm_mma<1>,
                         cudaFuncAttributeMaxDynamicSharedMemorySize, GEMM_SMEM);

    prep_kernel<<<(BIAS_ELEMS + 255) / 256, 256, 0, stream>>>(rel, btab, w_qkv, w_out);
    pack_a_kernel<0><<<A_PK / 256, 256, 0, stream>>>(x);

    {
        dim3 grid(9, MROWS / 128);
        gemm_mma<0><<<grid, 256, GEMM_SMEM, stream>>>(b_qkv, nullptr);
    }

    attn_kernel<<<NW * NH, 288, 0, stream>>>(mask);

    pack_a_kernel<1><<<A_PK / 256, 256, 0, stream>>>(nullptr);
    {
        dim3 grid(3, MROWS / 128);
        gemm_mma<1><<<grid, 256, GEMM_SMEM, stream>>>(b_out, out);
    }
}